// round 1
// baseline (speedup 1.0000x reference)
#include <cuda_runtime.h>
#include <math.h>

#define SEQ    2048
#define BATCH  2
#define HIDDEN 2048
#define NH     16
#define NKV    4
#define HD     128
#define ROWS   (BATCH*SEQ)   /* 4096 */
#define QDIM   (NH*HD)       /* 2048 */
#define KVDIM  (NKV*HD)      /* 512  */

// ---------------- scratch (device globals: no allocation allowed) ----------
__device__ float g_q[ROWS*QDIM];      // 32 MB
__device__ float g_k[ROWS*KVDIM];     //  8 MB
__device__ float g_v[ROWS*KVDIM];     //  8 MB
__device__ float g_attn[ROWS*QDIM];   // 32 MB
__device__ float g_cos[SEQ*64];
__device__ float g_sin[SEQ*64];

// ---------------- RoPE table (fp64 for bit-accuracy margin) ----------------
__global__ void rope_table_kernel() {
    int i = blockIdx.x * blockDim.x + threadIdx.x;
    if (i >= SEQ*64) return;
    int s = i >> 6, d = i & 63;
    double invf = pow(10000.0, -((double)d) / 64.0);
    double ang  = (double)s * invf;
    double sn, cs;
    sincos(ang, &sn, &cs);
    g_cos[i] = (float)cs;
    g_sin[i] = (float)sn;
}

// ---------------- RoPE apply (in-place on Q or K) --------------------------
__global__ void rope_apply_kernel(float* __restrict__ q, int nheads) {
    int i = blockIdx.x * blockDim.x + threadIdx.x;
    int total = ROWS * nheads * 64;
    if (i >= total) return;
    int d   = i & 63;
    int h   = (i >> 6) % nheads;
    int row = i / (nheads * 64);
    int s   = row & (SEQ - 1);
    float c  = g_cos[s*64 + d];
    float sn = g_sin[s*64 + d];
    float* base = q + (size_t)row * (nheads*128) + h*128;
    float x1 = base[d], x2 = base[d+64];
    base[d]    = x1*c - x2*sn;
    base[d+64] = x2*c + x1*sn;
}

// ---------------- classic SGEMM: C[M,N] = A[M,K] @ B[K,N] ------------------
// BM=BN=128, BK=8, 256 threads, 8x8 per-thread tile split as 4+4 (stride 64)
__global__ __launch_bounds__(256) void sgemm_kernel(
    const float* __restrict__ A, const float* __restrict__ B,
    float* __restrict__ C, int M, int N, int K)
{
    __shared__ float As[8][128];
    __shared__ float Bs[8][128];

    const int bx = blockIdx.x;      // N tile
    const int by = blockIdx.y;      // M tile
    const int tid = threadIdx.x;
    const int tx = tid & 15;        // 0..15 (cols)
    const int ty = tid >> 4;        // 0..15 (rows)

    const int a_row = tid >> 1;           // 0..127
    const int a_col = (tid & 1) * 4;      // 0 or 4
    const int b_row = tid >> 5;           // 0..7
    const int b_col = (tid & 31) * 4;     // 0..124

    const float* Ab = A + (size_t)(by*128) * K;
    const float* Bb = B + bx*128;

    float acc[8][8];
    #pragma unroll
    for (int i = 0; i < 8; i++)
        #pragma unroll
        for (int j = 0; j < 8; j++) acc[i][j] = 0.f;

    for (int k0 = 0; k0 < K; k0 += 8) {
        float4 a4 = *(const float4*)(Ab + (size_t)a_row*K + k0 + a_col);
        As[a_col+0][a_row] = a4.x;
        As[a_col+1][a_row] = a4.y;
        As[a_col+2][a_row] = a4.z;
        As[a_col+3][a_row] = a4.w;
        *(float4*)&Bs[b_row][b_col] = *(const float4*)(Bb + (size_t)(k0 + b_row)*N + b_col);
        __syncthreads();

        #pragma unroll
        for (int kk = 0; kk < 8; kk++) {
            float4 A0 = *(const float4*)&As[kk][ty*4];
            float4 A1 = *(const float4*)&As[kk][64 + ty*4];
            float4 B0 = *(const float4*)&Bs[kk][tx*4];
            float4 B1 = *(const float4*)&Bs[kk][64 + tx*4];
            float ar[8] = {A0.x,A0.y,A0.z,A0.w, A1.x,A1.y,A1.z,A1.w};
            float br[8] = {B0.x,B0.y,B0.z,B0.w, B1.x,B1.y,B1.z,B1.w};
            #pragma unroll
            for (int i = 0; i < 8; i++)
                #pragma unroll
                for (int j = 0; j < 8; j++)
                    acc[i][j] += ar[i] * br[j];
        }
        __syncthreads();
    }

    float* Cb = C + (size_t)(by*128) * N + bx*128;
    #pragma unroll
    for (int i = 0; i < 8; i++) {
        int r = (i < 4) ? (ty*4 + i) : (64 + ty*4 + i - 4);
        float4 v0 = make_float4(acc[i][0], acc[i][1], acc[i][2], acc[i][3]);
        float4 v1 = make_float4(acc[i][4], acc[i][5], acc[i][6], acc[i][7]);
        *(float4*)&Cb[(size_t)r*N + tx*4]      = v0;
        *(float4*)&Cb[(size_t)r*N + 64 + tx*4] = v1;
    }
}

// ---------------- flash attention (fp32, causal, GQA) ----------------------
// BM=BN=64, D=128, 256 threads. smem: Qs[64][132] + KVs[64][132] + Ps[64][68]
#define FLASH_SMEM ((2*64*132 + 64*68) * 4)

__global__ __launch_bounds__(256) void flash_kernel(
    const float* __restrict__ Q, const float* __restrict__ K,
    const float* __restrict__ V, float* __restrict__ O)
{
    extern __shared__ float sm[];
    float* Qs  = sm;                 // 64 x 132
    float* KVs = sm + 64*132;        // 64 x 132 (K then reused for V)
    float* Ps  = sm + 2*64*132;      // 64 x 68

    const int tid = threadIdx.x;
    const int qt = blockIdx.x, h = blockIdx.y, b = blockIdx.z;
    const int q0 = qt * 64;
    const int g = tid >> 4;          // row group: rows g*4 .. g*4+3
    const int c = tid & 15;          // col group
    const int hk = h >> 2;
    const float scale = 0.08838834764831845f;  // 1/sqrt(128)

    // load Q tile (64 rows x 128)
    const float* Qbase = Q + (size_t)(b*SEQ + q0) * QDIM + h*128;
    for (int v = tid; v < 64*32; v += 256) {
        int r = v >> 5, c4 = (v & 31) * 4;
        *(float4*)&Qs[r*132 + c4] = *(const float4*)(Qbase + (size_t)r*QDIM + c4);
    }

    float m[4], l[4], o[4][8];
    #pragma unroll
    for (int i = 0; i < 4; i++) {
        m[i] = -INFINITY; l[i] = 0.f;
        #pragma unroll
        for (int j = 0; j < 8; j++) o[i][j] = 0.f;
    }

    for (int kt = 0; kt <= qt; kt++) {
        __syncthreads();   // prev-iter PV done with KVs; Q load visible (iter 0)
        const float* Kbase = K + (size_t)(b*SEQ + kt*64) * KVDIM + hk*128;
        for (int v = tid; v < 64*32; v += 256) {
            int r = v >> 5, c4 = (v & 31) * 4;
            *(float4*)&KVs[r*132 + c4] = *(const float4*)(Kbase + (size_t)r*KVDIM + c4);
        }
        __syncthreads();

        // scores: thread owns rows g*4+i, cols c + j*16 (interleaved)
        float s[4][4];
        #pragma unroll
        for (int i = 0; i < 4; i++)
            #pragma unroll
            for (int j = 0; j < 4; j++) s[i][j] = 0.f;

        for (int kk = 0; kk < 128; kk += 4) {
            float4 qa[4], kb[4];
            #pragma unroll
            for (int i = 0; i < 4; i++) qa[i] = *(const float4*)&Qs[(g*4+i)*132 + kk];
            #pragma unroll
            for (int j = 0; j < 4; j++) kb[j] = *(const float4*)&KVs[(j*16+c)*132 + kk];
            #pragma unroll
            for (int i = 0; i < 4; i++)
                #pragma unroll
                for (int j = 0; j < 4; j++)
                    s[i][j] += qa[i].x*kb[j].x + qa[i].y*kb[j].y
                             + qa[i].z*kb[j].z + qa[i].w*kb[j].w;
        }

        const bool diag = (kt == qt);
        #pragma unroll
        for (int i = 0; i < 4; i++)
            #pragma unroll
            for (int j = 0; j < 4; j++) {
                s[i][j] *= scale;
                if (diag && (kt*64 + j*16 + c) > (q0 + g*4 + i)) s[i][j] = -INFINITY;
            }

        // online softmax (16-lane shuffle reductions inside each half-warp)
        #pragma unroll
        for (int i = 0; i < 4; i++) {
            float rm = fmaxf(fmaxf(s[i][0], s[i][1]), fmaxf(s[i][2], s[i][3]));
            #pragma unroll
            for (int off = 8; off; off >>= 1)
                rm = fmaxf(rm, __shfl_xor_sync(0xffffffffu, rm, off));
            float mn = fmaxf(m[i], rm);
            float alpha = expf(m[i] - mn);
            float rs = 0.f;
            #pragma unroll
            for (int j = 0; j < 4; j++) {
                float p = expf(s[i][j] - mn);
                Ps[(g*4+i)*68 + j*16 + c] = p;
                rs += p;
            }
            #pragma unroll
            for (int off = 8; off; off >>= 1)
                rs += __shfl_xor_sync(0xffffffffu, rs, off);
            l[i] = l[i]*alpha + rs;
            m[i] = mn;
            #pragma unroll
            for (int j = 0; j < 8; j++) o[i][j] *= alpha;
        }
        __syncthreads();   // everyone done with K + Ps written

        // load V tile over K
        const float* Vbase = V + (size_t)(b*SEQ + kt*64) * KVDIM + hk*128;
        for (int v = tid; v < 64*32; v += 256) {
            int r = v >> 5, c4 = (v & 31) * 4;
            *(float4*)&KVs[r*132 + c4] = *(const float4*)(Vbase + (size_t)r*KVDIM + c4);
        }
        __syncthreads();

        // PV: thread owns rows g*4+i, cols {c*4..+3, 64+c*4..+3}
        #pragma unroll 4
        for (int j = 0; j < 64; j += 4) {
            float4 p4[4];
            #pragma unroll
            for (int i = 0; i < 4; i++) p4[i] = *(const float4*)&Ps[(g*4+i)*68 + j];
            #pragma unroll
            for (int jj = 0; jj < 4; jj++) {
                float4 v0 = *(const float4*)&KVs[(j+jj)*132 + c*4];
                float4 v1 = *(const float4*)&KVs[(j+jj)*132 + 64 + c*4];
                #pragma unroll
                for (int i = 0; i < 4; i++) {
                    float p = (jj == 0) ? p4[i].x : (jj == 1) ? p4[i].y
                             : (jj == 2) ? p4[i].z : p4[i].w;
                    o[i][0] += p*v0.x; o[i][1] += p*v0.y;
                    o[i][2] += p*v0.z; o[i][3] += p*v0.w;
                    o[i][4] += p*v1.x; o[i][5] += p*v1.y;
                    o[i][6] += p*v1.z; o[i][7] += p*v1.w;
                }
            }
        }
    }

    // epilogue
    float* Obase = O + (size_t)(b*SEQ + q0) * QDIM + h*128;
    #pragma unroll
    for (int i = 0; i < 4; i++) {
        float inv = 1.f / l[i];
        int r = g*4 + i;
        float4 v0 = make_float4(o[i][0]*inv, o[i][1]*inv, o[i][2]*inv, o[i][3]*inv);
        float4 v1 = make_float4(o[i][4]*inv, o[i][5]*inv, o[i][6]*inv, o[i][7]*inv);
        *(float4*)&Obase[(size_t)r*QDIM + c*4]      = v0;
        *(float4*)&Obase[(size_t)r*QDIM + 64 + c*4] = v1;
    }
}

// ---------------- launch ---------------------------------------------------
extern "C" void kernel_launch(void* const* d_in, const int* in_sizes, int n_in,
                              void* d_out, int out_size)
{
    const float* x  = (const float*)d_in[0];
    const float* Wq = (const float*)d_in[1];
    const float* Wk = (const float*)d_in[2];
    const float* Wv = (const float*)d_in[3];
    const float* Wo = (const float*)d_in[4];
    float* out = (float*)d_out;

    float *qp, *kp, *vp, *ap;
    cudaGetSymbolAddress((void**)&qp, g_q);
    cudaGetSymbolAddress((void**)&kp, g_k);
    cudaGetSymbolAddress((void**)&vp, g_v);
    cudaGetSymbolAddress((void**)&ap, g_attn);

    // RoPE tables
    rope_table_kernel<<<(SEQ*64 + 255)/256, 256>>>();

    // projections
    sgemm_kernel<<<dim3(QDIM/128,  ROWS/128), 256>>>(x, Wq, qp, ROWS, QDIM,  HIDDEN);
    sgemm_kernel<<<dim3(KVDIM/128, ROWS/128), 256>>>(x, Wk, kp, ROWS, KVDIM, HIDDEN);
    sgemm_kernel<<<dim3(KVDIM/128, ROWS/128), 256>>>(x, Wv, vp, ROWS, KVDIM, HIDDEN);

    // RoPE
    rope_apply_kernel<<<(ROWS*NH*64 + 255)/256, 256>>>(qp, NH);
    rope_apply_kernel<<<(ROWS*NKV*64 + 255)/256, 256>>>(kp, NKV);

    // attention
    cudaFuncSetAttribute(flash_kernel, cudaFuncAttributeMaxDynamicSharedMemorySize,
                         FLASH_SMEM);
    flash_kernel<<<dim3(SEQ/64, NH, BATCH), 256, FLASH_SMEM>>>(qp, kp, vp, ap);

    // output projection
    sgemm_kernel<<<dim3(QDIM/128, ROWS/128), 256>>>(ap, Wo, out, ROWS, QDIM, HIDDEN);
}

// round 3
// speedup vs baseline: 3.2080x; 3.2080x over previous
#include <cuda_runtime.h>
#include <math.h>

#define SEQ    2048
#define BATCH  2
#define HIDDEN 2048
#define NH     16
#define NKV    4
#define HD     128
#define ROWS   (BATCH*SEQ)   /* 4096 */
#define QDIM   (NH*HD)       /* 2048 */
#define KVDIM  (NKV*HD)      /* 512  */

// ---------------- scratch (device globals: no allocation allowed) ----------
__device__ float g_q[ROWS*QDIM];      // 32 MB
__device__ float g_k[ROWS*KVDIM];     //  8 MB
__device__ float g_v[ROWS*KVDIM];     //  8 MB
__device__ float g_attn[ROWS*QDIM];   // 32 MB
__device__ float g_cos[SEQ*64];
__device__ float g_sin[SEQ*64];

// ---------------- helpers ---------------------------------------------------
__device__ __forceinline__ unsigned f2tf(float x) {
    unsigned u; asm("cvt.rna.tf32.f32 %0, %1;" : "=r"(u) : "f"(x)); return u;
}
__device__ __forceinline__ void mma8(float* d, unsigned a0, unsigned a1,
                                     unsigned a2, unsigned a3,
                                     unsigned b0, unsigned b1) {
    asm volatile("mma.sync.aligned.m16n8k8.row.col.f32.tf32.tf32.f32 "
        "{%0,%1,%2,%3}, {%4,%5,%6,%7}, {%8,%9}, {%0,%1,%2,%3};"
        : "+f"(d[0]), "+f"(d[1]), "+f"(d[2]), "+f"(d[3])
        : "r"(a0), "r"(a1), "r"(a2), "r"(a3), "r"(b0), "r"(b1));
}
__device__ __forceinline__ void cpa16(float* smem, const float* g) {
    unsigned s = (unsigned)__cvta_generic_to_shared(smem);
    asm volatile("cp.async.cg.shared.global [%0], [%1], 16;" :: "r"(s), "l"(g));
}
__device__ __forceinline__ void cpcommit() { asm volatile("cp.async.commit_group;"); }
template<int N> __device__ __forceinline__ void cpwait() {
    asm volatile("cp.async.wait_group %0;" :: "n"(N));
}

// ---------------- RoPE table -----------------------------------------------
__global__ void rope_table_kernel() {
    int i = blockIdx.x * blockDim.x + threadIdx.x;
    if (i >= SEQ*64) return;
    int s = i >> 6, d = i & 63;
    double invf = pow(10000.0, -((double)d) / 64.0);
    double ang  = (double)s * invf;
    double sn, cs;
    sincos(ang, &sn, &cs);
    g_cos[i] = (float)cs;
    g_sin[i] = (float)sn;
}

__global__ void rope_apply_kernel(float* __restrict__ q, int nheads) {
    int i = blockIdx.x * blockDim.x + threadIdx.x;
    int total = ROWS * nheads * 64;
    if (i >= total) return;
    int d   = i & 63;
    int h   = (i >> 6) % nheads;
    int row = i / (nheads * 64);
    int s   = row & (SEQ - 1);
    float c  = g_cos[s*64 + d];
    float sn = g_sin[s*64 + d];
    float* base = q + (size_t)row * (nheads*128) + h*128;
    float x1 = base[d], x2 = base[d+64];
    base[d]    = x1*c - x2*sn;
    base[d+64] = x2*c + x1*sn;
}

// ---------------- tf32 GEMM: C[M,N] = A[M,K] @ B[K,N] ----------------------
// 128x128x16 tile, 8 warps (2x4), warp tile 64x32, cp.async double buffer.
#define AS_ST 20
#define BS_ST 136

__global__ __launch_bounds__(256) void gemm_tf32(
    const float* __restrict__ A, const float* __restrict__ B,
    float* __restrict__ C, int M, int N, int K)
{
    __shared__ float As[2][128*AS_ST];
    __shared__ float Bs[2][16*BS_ST];

    const int tid  = threadIdx.x;
    const int lane = tid & 31, warp = tid >> 5;
    const int wm = warp >> 2, wn = warp & 3;         // 2 x 4 warps
    const int bx = blockIdx.x, by = blockIdx.y;
    const int lq = lane >> 2, lr = lane & 3;

    const float* Ab = A + (size_t)(by*128)*K;
    const float* Bb = B + (size_t)bx*128;

    float acc[4][4][4];
    #pragma unroll
    for (int i = 0; i < 4; i++)
        #pragma unroll
        for (int j = 0; j < 4; j++)
            #pragma unroll
            for (int t = 0; t < 4; t++) acc[i][j][t] = 0.f;

    // A tile: 128x16 = 512 16B-chunks (m = c>>2, kc = c&3)
    // B tile: 16x128 = 512 16B-chunks (k = c>>5, nc = c&31)
    #define LOAD_STAGE(buf, k0) do {                                          \
        _Pragma("unroll")                                                     \
        for (int i = 0; i < 2; i++) {                                         \
            int c = tid + i*256;                                              \
            int m = c >> 2, kc = c & 3;                                       \
            cpa16(&As[buf][m*AS_ST + kc*4], Ab + (size_t)m*K + (k0) + kc*4);  \
        }                                                                     \
        _Pragma("unroll")                                                     \
        for (int i = 0; i < 2; i++) {                                         \
            int c = tid + i*256;                                              \
            int k = c >> 5, nc = c & 31;                                      \
            cpa16(&Bs[buf][k*BS_ST + nc*4], Bb + (size_t)((k0)+k)*N + nc*4);  \
        }                                                                     \
        cpcommit();                                                           \
    } while (0)

    LOAD_STAGE(0, 0);

    const int nIter = K / 16;
    for (int it = 0; it < nIter; it++) {
        int buf = it & 1;
        if (it + 1 < nIter) { LOAD_STAGE(buf ^ 1, (it+1)*16); cpwait<1>(); }
        else                { cpwait<0>(); }
        __syncthreads();

        #pragma unroll
        for (int kk = 0; kk < 16; kk += 8) {
            unsigned a[4][4], b[4][2];
            #pragma unroll
            for (int mt = 0; mt < 4; mt++) {
                int m = wm*64 + mt*16 + lq;
                a[mt][0] = f2tf(As[buf][ m      *AS_ST + kk + lr    ]);
                a[mt][1] = f2tf(As[buf][(m + 8)*AS_ST + kk + lr    ]);
                a[mt][2] = f2tf(As[buf][ m      *AS_ST + kk + lr + 4]);
                a[mt][3] = f2tf(As[buf][(m + 8)*AS_ST + kk + lr + 4]);
            }
            #pragma unroll
            for (int nt = 0; nt < 4; nt++) {
                int n = wn*32 + nt*8 + lq;
                b[nt][0] = f2tf(Bs[buf][(kk + lr    )*BS_ST + n]);
                b[nt][1] = f2tf(Bs[buf][(kk + lr + 4)*BS_ST + n]);
            }
            #pragma unroll
            for (int mt = 0; mt < 4; mt++)
                #pragma unroll
                for (int nt = 0; nt < 4; nt++)
                    mma8(acc[mt][nt], a[mt][0], a[mt][1], a[mt][2], a[mt][3],
                         b[nt][0], b[nt][1]);
        }
        __syncthreads();
    }

    #pragma unroll
    for (int mt = 0; mt < 4; mt++) {
        int row = by*128 + wm*64 + mt*16 + lq;
        #pragma unroll
        for (int nt = 0; nt < 4; nt++) {
            int col = bx*128 + wn*32 + nt*8 + lr*2;
            float2 v0 = make_float2(acc[mt][nt][0], acc[mt][nt][1]);
            float2 v1 = make_float2(acc[mt][nt][2], acc[mt][nt][3]);
            *(float2*)&C[(size_t) row     *N + col] = v0;
            *(float2*)&C[(size_t)(row + 8)*N + col] = v1;
        }
    }
    #undef LOAD_STAGE
}

// ---------------- flash attention, tf32 mma --------------------------------
// BM=128 (8 warps x 16 rows), BN=64, D=128.
#define QS_ST 132
#define KS_ST 132
#define VS_ST 136
#define PS_ST 68
#define QS_OFF 0
#define KS_OFF (128*QS_ST)
#define VS_OFF (KS_OFF + 64*KS_ST)
#define PS_OFF (VS_OFF + 64*VS_ST)
#define FLASH_SMEM_BYTES ((PS_OFF + 128*PS_ST)*4)   /* 171008 */

__global__ __launch_bounds__(256) void flash_tf32(
    const float* __restrict__ Q, const float* __restrict__ K,
    const float* __restrict__ V, float* __restrict__ O)
{
    extern __shared__ float sm[];
    const int tid  = threadIdx.x;
    const int lane = tid & 31, w = tid >> 5;
    const int lq = lane >> 2, lr = lane & 3;
    const int qt = (gridDim.x - 1) - blockIdx.x;   // heavy tiles first
    const int h  = blockIdx.y, b = blockIdx.z;
    const int hk = h >> 2;
    const int q0 = qt * 128;
    const float scale = 0.08838834764831845f;

    const float* Qbase = Q + (size_t)(b*SEQ + q0)*QDIM + h*128;
    const float* Kb0   = K + (size_t)(b*SEQ)*KVDIM + hk*128;
    const float* Vb0   = V + (size_t)(b*SEQ)*KVDIM + hk*128;

    // Q tile: 128 rows x 128 cols = 4096 16B-chunks (m = c>>5, kc = c&31)
    #pragma unroll
    for (int i = 0; i < 16; i++) {
        int c = tid + i*256;
        int m = c >> 5, kc = c & 31;
        cpa16(&sm[QS_OFF + m*QS_ST + kc*4], Qbase + (size_t)m*QDIM + kc*4);
    }
    cpcommit();

    // K/V tile: 64 rows x 128 cols = 2048 16B-chunks (r = c>>5, kc = c&31)
    #define LOAD_K(kt) do {                                                    \
        const float* kb = Kb0 + (size_t)(kt)*64*KVDIM;                         \
        _Pragma("unroll")                                                      \
        for (int i = 0; i < 8; i++) {                                          \
            int c = tid + i*256;                                               \
            int r = c >> 5, kc = c & 31;                                       \
            cpa16(&sm[KS_OFF + r*KS_ST + kc*4], kb + (size_t)r*KVDIM + kc*4);  \
        }                                                                      \
        cpcommit();                                                            \
    } while (0)
    #define LOAD_V(kt) do {                                                    \
        const float* vb = Vb0 + (size_t)(kt)*64*KVDIM;                         \
        _Pragma("unroll")                                                      \
        for (int i = 0; i < 8; i++) {                                          \
            int c = tid + i*256;                                               \
            int r = c >> 5, kc = c & 31;                                       \
            cpa16(&sm[VS_OFF + r*VS_ST + kc*4], vb + (size_t)r*KVDIM + kc*4);  \
        }                                                                      \
        cpcommit();                                                            \
    } while (0)

    LOAD_K(0);
    LOAD_V(0);

    float o[16][4];
    #pragma unroll
    for (int nt = 0; nt < 16; nt++)
        #pragma unroll
        for (int t = 0; t < 4; t++) o[nt][t] = 0.f;
    float m0 = -INFINITY, m1 = -INFINITY, l0 = 0.f, l1 = 0.f;

    const int nkt = 2*qt + 2;
    const int mrow = w*16 + lq;

    for (int kt = 0; kt < nkt; kt++) {
        cpwait<1>();          // kt=0: retire Q,K (V pending); else: retire K
        __syncthreads();

        // -------- scores S = Q K^T --------
        float s[8][4];
        #pragma unroll
        for (int nt = 0; nt < 8; nt++)
            #pragma unroll
            for (int t = 0; t < 4; t++) s[nt][t] = 0.f;

        #pragma unroll
        for (int kk = 0; kk < 128; kk += 8) {
            unsigned a0 = f2tf(sm[QS_OFF +  mrow     *QS_ST + kk + lr    ]);
            unsigned a1 = f2tf(sm[QS_OFF + (mrow + 8)*QS_ST + kk + lr    ]);
            unsigned a2 = f2tf(sm[QS_OFF +  mrow     *QS_ST + kk + lr + 4]);
            unsigned a3 = f2tf(sm[QS_OFF + (mrow + 8)*QS_ST + kk + lr + 4]);
            #pragma unroll
            for (int nt = 0; nt < 8; nt++) {
                int n = nt*8 + lq;
                unsigned b0 = f2tf(sm[KS_OFF + n*KS_ST + kk + lr    ]);
                unsigned b1 = f2tf(sm[KS_OFF + n*KS_ST + kk + lr + 4]);
                mma8(s[nt], a0, a1, a2, a3, b0, b1);
            }
        }

        // -------- scale + causal mask --------
        const int r0 = q0 + mrow, r1 = r0 + 8;
        const bool need_mask = (kt >= 2*qt);
        #pragma unroll
        for (int nt = 0; nt < 8; nt++) {
            int col = kt*64 + nt*8 + lr*2;
            s[nt][0] *= scale; s[nt][1] *= scale;
            s[nt][2] *= scale; s[nt][3] *= scale;
            if (need_mask) {
                if (col     > r0) s[nt][0] = -INFINITY;
                if (col + 1 > r0) s[nt][1] = -INFINITY;
                if (col     > r1) s[nt][2] = -INFINITY;
                if (col + 1 > r1) s[nt][3] = -INFINITY;
            }
        }

        // -------- online softmax (quad-level rows) --------
        float mx0 = -INFINITY, mx1 = -INFINITY;
        #pragma unroll
        for (int nt = 0; nt < 8; nt++) {
            mx0 = fmaxf(mx0, fmaxf(s[nt][0], s[nt][1]));
            mx1 = fmaxf(mx1, fmaxf(s[nt][2], s[nt][3]));
        }
        mx0 = fmaxf(mx0, __shfl_xor_sync(0xffffffffu, mx0, 1));
        mx0 = fmaxf(mx0, __shfl_xor_sync(0xffffffffu, mx0, 2));
        mx1 = fmaxf(mx1, __shfl_xor_sync(0xffffffffu, mx1, 1));
        mx1 = fmaxf(mx1, __shfl_xor_sync(0xffffffffu, mx1, 2));
        float mn0 = fmaxf(m0, mx0), mn1 = fmaxf(m1, mx1);
        float al0 = __expf(m0 - mn0), al1 = __expf(m1 - mn1);

        float rs0 = 0.f, rs1 = 0.f;
        #pragma unroll
        for (int nt = 0; nt < 8; nt++) {
            float p0 = __expf(s[nt][0] - mn0);
            float p1 = __expf(s[nt][1] - mn0);
            float p2 = __expf(s[nt][2] - mn1);
            float p3 = __expf(s[nt][3] - mn1);
            rs0 += p0 + p1; rs1 += p2 + p3;
            int colb = nt*8 + lr*2;
            *(float2*)&sm[PS_OFF +  mrow     *PS_ST + colb] = make_float2(p0, p1);
            *(float2*)&sm[PS_OFF + (mrow + 8)*PS_ST + colb] = make_float2(p2, p3);
        }
        rs0 += __shfl_xor_sync(0xffffffffu, rs0, 1);
        rs0 += __shfl_xor_sync(0xffffffffu, rs0, 2);
        rs1 += __shfl_xor_sync(0xffffffffu, rs1, 1);
        rs1 += __shfl_xor_sync(0xffffffffu, rs1, 2);
        l0 = l0*al0 + rs0;  l1 = l1*al1 + rs1;
        m0 = mn0;           m1 = mn1;
        #pragma unroll
        for (int nt = 0; nt < 16; nt++) {
            o[nt][0] *= al0; o[nt][1] *= al0;
            o[nt][2] *= al1; o[nt][3] *= al1;
        }

        __syncthreads();   // Ps written, everyone done reading Ks

        if (kt + 1 < nkt) { LOAD_K(kt + 1); cpwait<1>(); } // retire V(kt)
        else              { cpwait<0>(); }
        __syncthreads();   // V visible

        // -------- PV --------
        #pragma unroll
        for (int kk = 0; kk < 64; kk += 8) {
            unsigned a0 = f2tf(sm[PS_OFF +  mrow     *PS_ST + kk + lr    ]);
            unsigned a1 = f2tf(sm[PS_OFF + (mrow + 8)*PS_ST + kk + lr    ]);
            unsigned a2 = f2tf(sm[PS_OFF +  mrow     *PS_ST + kk + lr + 4]);
            unsigned a3 = f2tf(sm[PS_OFF + (mrow + 8)*PS_ST + kk + lr + 4]);
            #pragma unroll
            for (int nt = 0; nt < 16; nt++) {
                int n = nt*8 + lq;
                unsigned b0 = f2tf(sm[VS_OFF + (kk + lr    )*VS_ST + n]);
                unsigned b1 = f2tf(sm[VS_OFF + (kk + lr + 4)*VS_ST + n]);
                mma8(o[nt], a0, a1, a2, a3, b0, b1);
            }
        }
        __syncthreads();   // everyone done reading Vs

        if (kt + 1 < nkt) LOAD_V(kt + 1);
    }

    // -------- epilogue --------
    float inv0 = 1.f / l0, inv1 = 1.f / l1;
    float* Ob = O + (size_t)(b*SEQ + q0)*QDIM + h*128;
    #pragma unroll
    for (int nt = 0; nt < 16; nt++) {
        int col = nt*8 + lr*2;
        *(float2*)&Ob[(size_t) mrow     *QDIM + col] =
            make_float2(o[nt][0]*inv0, o[nt][1]*inv0);
        *(float2*)&Ob[(size_t)(mrow + 8)*QDIM + col] =
            make_float2(o[nt][2]*inv1, o[nt][3]*inv1);
    }
    #undef LOAD_K
    #undef LOAD_V
}

// ---------------- launch ---------------------------------------------------
extern "C" void kernel_launch(void* const* d_in, const int* in_sizes, int n_in,
                              void* d_out, int out_size)
{
    const float* x  = (const float*)d_in[0];
    const float* Wq = (const float*)d_in[1];
    const float* Wk = (const float*)d_in[2];
    const float* Wv = (const float*)d_in[3];
    const float* Wo = (const float*)d_in[4];
    float* out = (float*)d_out;

    float *qp, *kp, *vp, *ap;
    cudaGetSymbolAddress((void**)&qp, g_q);
    cudaGetSymbolAddress((void**)&kp, g_k);
    cudaGetSymbolAddress((void**)&vp, g_v);
    cudaGetSymbolAddress((void**)&ap, g_attn);

    rope_table_kernel<<<(SEQ*64 + 255)/256, 256>>>();

    gemm_tf32<<<dim3(QDIM/128,  ROWS/128), 256>>>(x, Wq, qp, ROWS, QDIM,  HIDDEN);
    gemm_tf32<<<dim3(KVDIM/128, ROWS/128), 256>>>(x, Wk, kp, ROWS, KVDIM, HIDDEN);
    gemm_tf32<<<dim3(KVDIM/128, ROWS/128), 256>>>(x, Wv, vp, ROWS, KVDIM, HIDDEN);

    rope_apply_kernel<<<(ROWS*NH*64 + 255)/256, 256>>>(qp, NH);
    rope_apply_kernel<<<(ROWS*NKV*64 + 255)/256, 256>>>(kp, NKV);

    cudaFuncSetAttribute(flash_tf32, cudaFuncAttributeMaxDynamicSharedMemorySize,
                         FLASH_SMEM_BYTES);
    flash_tf32<<<dim3(SEQ/128, NH, BATCH), 256, FLASH_SMEM_BYTES>>>(qp, kp, vp, ap);

    gemm_tf32<<<dim3(QDIM/128, ROWS/128), 256>>>(ap, Wo, out, ROWS, QDIM, HIDDEN);
}

// round 4
// speedup vs baseline: 5.8743x; 1.8311x over previous
#include <cuda_runtime.h>
#include <cuda_fp16.h>
#include <math.h>

#define SEQ    2048
#define BATCH  2
#define HIDDEN 2048
#define NH     16
#define NKV    4
#define HD     128
#define ROWS   (BATCH*SEQ)   /* 4096 */
#define QDIM   (NH*HD)       /* 2048 */
#define KVDIM  (NKV*HD)      /* 512  */

// ---------------- scratch (device globals: no allocation allowed) ----------
__device__ __half g_xh[ROWS*HIDDEN];    // 16 MB
__device__ __half g_wqh[HIDDEN*QDIM];   //  8 MB
__device__ __half g_wkh[HIDDEN*KVDIM];  //  2 MB
__device__ __half g_wvh[HIDDEN*KVDIM];  //  2 MB
__device__ __half g_woh[QDIM*HIDDEN];   //  8 MB
__device__ __half g_qh[ROWS*QDIM];      // 16 MB
__device__ __half g_kh[ROWS*KVDIM];     //  4 MB
__device__ __half g_vh[ROWS*KVDIM];     //  4 MB
__device__ __half g_ah[ROWS*QDIM];      // 16 MB
__device__ float  g_cos[SEQ*64];
__device__ float  g_sin[SEQ*64];

// ---------------- asm helpers ----------------------------------------------
__device__ __forceinline__ void ldsm4(unsigned* r, const void* p) {
    unsigned a = (unsigned)__cvta_generic_to_shared(p);
    asm volatile("ldmatrix.sync.aligned.m8n8.x4.shared.b16 {%0,%1,%2,%3}, [%4];"
        : "=r"(r[0]), "=r"(r[1]), "=r"(r[2]), "=r"(r[3]) : "r"(a));
}
__device__ __forceinline__ void ldsm4t(unsigned* r, const void* p) {
    unsigned a = (unsigned)__cvta_generic_to_shared(p);
    asm volatile("ldmatrix.sync.aligned.m8n8.x4.trans.shared.b16 {%0,%1,%2,%3}, [%4];"
        : "=r"(r[0]), "=r"(r[1]), "=r"(r[2]), "=r"(r[3]) : "r"(a));
}
__device__ __forceinline__ void mma16(float* d, const unsigned* a,
                                      unsigned b0, unsigned b1) {
    asm volatile("mma.sync.aligned.m16n8k16.row.col.f32.f16.f16.f32 "
        "{%0,%1,%2,%3}, {%4,%5,%6,%7}, {%8,%9}, {%0,%1,%2,%3};"
        : "+f"(d[0]), "+f"(d[1]), "+f"(d[2]), "+f"(d[3])
        : "r"(a[0]), "r"(a[1]), "r"(a[2]), "r"(a[3]), "r"(b0), "r"(b1));
}
__device__ __forceinline__ void cpa16(const void* smem, const void* g) {
    unsigned s = (unsigned)__cvta_generic_to_shared(smem);
    asm volatile("cp.async.cg.shared.global [%0], [%1], 16;" :: "r"(s), "l"(g));
}
__device__ __forceinline__ void cpcommit() { asm volatile("cp.async.commit_group;"); }
template<int N> __device__ __forceinline__ void cpwait() {
    asm volatile("cp.async.wait_group %0;" :: "n"(N));
}

// ---------------- fp32 -> fp16 convert -------------------------------------
__global__ void f2h_kernel(const float4* __restrict__ src,
                           __half2* __restrict__ dst, int n4) {
    int i = blockIdx.x * blockDim.x + threadIdx.x;
    if (i >= n4) return;
    float4 v = src[i];
    dst[2*i]   = __floats2half2_rn(v.x, v.y);
    dst[2*i+1] = __floats2half2_rn(v.z, v.w);
}

// ---------------- RoPE -------------------------------------------------------
__global__ void rope_table_kernel() {
    int i = blockIdx.x * blockDim.x + threadIdx.x;
    if (i >= SEQ*64) return;
    int s = i >> 6, d = i & 63;
    double invf = pow(10000.0, -((double)d) / 64.0);
    double ang  = (double)s * invf;
    double sn, cs;
    sincos(ang, &sn, &cs);
    g_cos[i] = (float)cs;
    g_sin[i] = (float)sn;
}

__global__ void rope_apply_h(__half* __restrict__ q, int nheads) {
    int i = blockIdx.x * blockDim.x + threadIdx.x;
    int total = ROWS * nheads * 64;
    if (i >= total) return;
    int d   = i & 63;
    int h   = (i >> 6) % nheads;
    int row = i / (nheads * 64);
    int s   = row & (SEQ - 1);
    float c  = g_cos[s*64 + d];
    float sn = g_sin[s*64 + d];
    __half* base = q + (size_t)row * (nheads*128) + h*128;
    float x1 = __half2float(base[d]), x2 = __half2float(base[d+64]);
    base[d]    = __float2half_rn(x1*c - x2*sn);
    base[d+64] = __float2half_rn(x2*c + x1*sn);
}

// ---------------- fp16 GEMM: C[M,N] = A[M,K] @ B[K,N] ----------------------
// 128x128x32 tile, 8 warps (2x4), warp tile 64x32, cp.async double buffer.
#define AST 40     /* halves; 80B = 5*16B, odd multiple -> ldsm conflict-free */
#define BST 136    /* halves; 272B = 17*16B */

template<int OUT_HALF>
__global__ __launch_bounds__(256) void gemm_f16(
    const __half* __restrict__ A, const __half* __restrict__ B,
    void* __restrict__ Cv, int M, int N, int K)
{
    __shared__ __half As[2][128*AST];
    __shared__ __half Bs[2][32*BST];

    const int tid  = threadIdx.x;
    const int l    = tid & 31, warp = tid >> 5;
    const int wm = warp >> 2, wn = warp & 3;
    const int bx = blockIdx.x, by = blockIdx.y;
    const int lq = l >> 2, lr = l & 3;

    const __half* Ab = A + (size_t)(by*128)*K;
    const __half* Bb = B + (size_t)bx*128;

    float acc[4][4][4];
    #pragma unroll
    for (int i = 0; i < 4; i++)
        #pragma unroll
        for (int j = 0; j < 4; j++)
            #pragma unroll
            for (int t = 0; t < 4; t++) acc[i][j][t] = 0.f;

    // A tile: 128x32 half = 512 16B-chunks (m = c>>2, kc = (c&3)*8)
    // B tile: 32x128 half = 512 16B-chunks (k = c>>4, nc = (c&15)*8)
    #define LOAD_STAGE(buf, k0) do {                                           \
        _Pragma("unroll")                                                      \
        for (int i = 0; i < 2; i++) {                                          \
            int c = tid + i*256;                                               \
            int m = c >> 2, kc = (c & 3) * 8;                                  \
            cpa16(&As[buf][m*AST + kc], Ab + (size_t)m*K + (k0) + kc);         \
        }                                                                      \
        _Pragma("unroll")                                                      \
        for (int i = 0; i < 2; i++) {                                          \
            int c = tid + i*256;                                               \
            int k = c >> 4, nc = (c & 15) * 8;                                 \
            cpa16(&Bs[buf][k*BST + nc], Bb + (size_t)((k0)+k)*N + nc);         \
        }                                                                      \
        cpcommit();                                                            \
    } while (0)

    LOAD_STAGE(0, 0);

    const int nIter = K / 32;
    for (int it = 0; it < nIter; it++) {
        int buf = it & 1;
        if (it + 1 < nIter) { LOAD_STAGE(buf ^ 1, (it+1)*32); cpwait<1>(); }
        else                { cpwait<0>(); }
        __syncthreads();

        #pragma unroll
        for (int kk = 0; kk < 32; kk += 16) {
            unsigned a[4][4], b[2][4];
            #pragma unroll
            for (int mt = 0; mt < 4; mt++) {
                int m0 = wm*64 + mt*16;
                ldsm4(a[mt], &As[buf][(m0 + (l & 15))*AST + kk + ((l >> 4) << 3)]);
            }
            #pragma unroll
            for (int g = 0; g < 2; g++) {
                int n0 = wn*32 + g*16;
                ldsm4t(b[g], &Bs[buf][(kk + (l & 15))*BST + n0 + ((l >> 4) << 3)]);
            }
            #pragma unroll
            for (int mt = 0; mt < 4; mt++)
                #pragma unroll
                for (int nt = 0; nt < 4; nt++) {
                    const unsigned* bg = b[nt >> 1];
                    if (nt & 1) mma16(acc[mt][nt], a[mt], bg[2], bg[3]);
                    else        mma16(acc[mt][nt], a[mt], bg[0], bg[1]);
                }
        }
        __syncthreads();
    }

    #pragma unroll
    for (int mt = 0; mt < 4; mt++) {
        int row = by*128 + wm*64 + mt*16 + lq;
        #pragma unroll
        for (int nt = 0; nt < 4; nt++) {
            int col = bx*128 + wn*32 + nt*8 + lr*2;
            if (OUT_HALF) {
                __half* C = (__half*)Cv;
                *(__half2*)&C[(size_t) row     *N + col] =
                    __floats2half2_rn(acc[mt][nt][0], acc[mt][nt][1]);
                *(__half2*)&C[(size_t)(row + 8)*N + col] =
                    __floats2half2_rn(acc[mt][nt][2], acc[mt][nt][3]);
            } else {
                float* C = (float*)Cv;
                *(float2*)&C[(size_t) row     *N + col] =
                    make_float2(acc[mt][nt][0], acc[mt][nt][1]);
                *(float2*)&C[(size_t)(row + 8)*N + col] =
                    make_float2(acc[mt][nt][2], acc[mt][nt][3]);
            }
        }
    }
    #undef LOAD_STAGE
}

// ---------------- flash attention, fp16 mma + ldmatrix ---------------------
// BM=128 (8 warps x 16 rows), BN=64, D=128. All smem in halves.
#define QST 136
#define KST 136
#define VST 136
#define PST 72
#define QS_OFF 0
#define KS_OFF (128*QST)              /* 17408 */
#define VS_OFF (KS_OFF + 64*KST)      /* 26112 */
#define PS_OFF (VS_OFF + 64*VST)      /* 34816 */
#define FLASH_SMEM ((PS_OFF + 128*PST)*2)   /* 88064 bytes */

__global__ __launch_bounds__(256) void flash_f16(
    const __half* __restrict__ Q, const __half* __restrict__ K,
    const __half* __restrict__ V, __half* __restrict__ O)
{
    extern __shared__ __half sh[];
    const int tid  = threadIdx.x;
    const int l    = tid & 31, w = tid >> 5;
    const int lq = l >> 2, lr = l & 3;
    const int qt = (gridDim.x - 1) - blockIdx.x;   // heavy tiles first
    const int h  = blockIdx.y, b = blockIdx.z;
    const int hk = h >> 2;
    const int q0 = qt * 128;
    const float scale = 0.08838834764831845f;

    const __half* Qbase = Q + (size_t)(b*SEQ + q0)*QDIM + h*128;
    const __half* Kb0   = K + (size_t)(b*SEQ)*KVDIM + hk*128;
    const __half* Vb0   = V + (size_t)(b*SEQ)*KVDIM + hk*128;

    // Q tile: 128 x 128 half = 2048 16B-chunks (m = c>>4, kc = (c&15)*8)
    #pragma unroll
    for (int i = 0; i < 8; i++) {
        int c = tid + i*256;
        int m = c >> 4, kc = (c & 15) * 8;
        cpa16(&sh[QS_OFF + m*QST + kc], Qbase + (size_t)m*QDIM + kc);
    }
    cpcommit();

    // K/V tile: 64 x 128 half = 1024 chunks (r = c>>4, kc = (c&15)*8)
    #define LOAD_K(kt) do {                                                    \
        const __half* kb = Kb0 + (size_t)(kt)*64*KVDIM;                        \
        _Pragma("unroll")                                                      \
        for (int i = 0; i < 4; i++) {                                          \
            int c = tid + i*256;                                               \
            int r = c >> 4, kc = (c & 15) * 8;                                 \
            cpa16(&sh[KS_OFF + r*KST + kc], kb + (size_t)r*KVDIM + kc);        \
        }                                                                      \
        cpcommit();                                                            \
    } while (0)
    #define LOAD_V(kt) do {                                                    \
        const __half* vb = Vb0 + (size_t)(kt)*64*KVDIM;                        \
        _Pragma("unroll")                                                      \
        for (int i = 0; i < 4; i++) {                                          \
            int c = tid + i*256;                                               \
            int r = c >> 4, kc = (c & 15) * 8;                                 \
            cpa16(&sh[VS_OFF + r*VST + kc], vb + (size_t)r*KVDIM + kc);        \
        }                                                                      \
        cpcommit();                                                            \
    } while (0)

    LOAD_K(0);
    LOAD_V(0);

    float o[16][4];
    #pragma unroll
    for (int nt = 0; nt < 16; nt++)
        #pragma unroll
        for (int t = 0; t < 4; t++) o[nt][t] = 0.f;
    float m0 = -INFINITY, m1 = -INFINITY, l0 = 0.f, l1 = 0.f;

    const int nkt  = 2*qt + 2;
    const int mrow = w*16 + lq;
    const int lidx = l & 15, lhi = (l >> 4) << 3;

    for (int kt = 0; kt < nkt; kt++) {
        cpwait<1>();
        __syncthreads();

        // -------- scores S = Q K^T --------
        float s[8][4];
        #pragma unroll
        for (int nt = 0; nt < 8; nt++)
            #pragma unroll
            for (int t = 0; t < 4; t++) s[nt][t] = 0.f;

        #pragma unroll
        for (int kk = 0; kk < 128; kk += 16) {
            unsigned a[4];
            ldsm4(a, &sh[QS_OFF + (w*16 + lidx)*QST + kk + lhi]);
            #pragma unroll
            for (int g = 0; g < 4; g++) {
                unsigned bk[4];
                int n0 = g*16;
                ldsm4(bk, &sh[KS_OFF + (n0 + ((l >> 4) << 3) + (l & 7))*KST
                               + kk + (((l >> 3) & 1) << 3)]);
                mma16(s[g*2],     a, bk[0], bk[1]);
                mma16(s[g*2 + 1], a, bk[2], bk[3]);
            }
        }

        // -------- scale + causal mask --------
        const int r0 = q0 + mrow, r1 = r0 + 8;
        const bool need_mask = (kt >= 2*qt);
        #pragma unroll
        for (int nt = 0; nt < 8; nt++) {
            int col = kt*64 + nt*8 + lr*2;
            s[nt][0] *= scale; s[nt][1] *= scale;
            s[nt][2] *= scale; s[nt][3] *= scale;
            if (need_mask) {
                if (col     > r0) s[nt][0] = -INFINITY;
                if (col + 1 > r0) s[nt][1] = -INFINITY;
                if (col     > r1) s[nt][2] = -INFINITY;
                if (col + 1 > r1) s[nt][3] = -INFINITY;
            }
        }

        // -------- online softmax --------
        float mx0 = -INFINITY, mx1 = -INFINITY;
        #pragma unroll
        for (int nt = 0; nt < 8; nt++) {
            mx0 = fmaxf(mx0, fmaxf(s[nt][0], s[nt][1]));
            mx1 = fmaxf(mx1, fmaxf(s[nt][2], s[nt][3]));
        }
        mx0 = fmaxf(mx0, __shfl_xor_sync(0xffffffffu, mx0, 1));
        mx0 = fmaxf(mx0, __shfl_xor_sync(0xffffffffu, mx0, 2));
        mx1 = fmaxf(mx1, __shfl_xor_sync(0xffffffffu, mx1, 1));
        mx1 = fmaxf(mx1, __shfl_xor_sync(0xffffffffu, mx1, 2));
        float mn0 = fmaxf(m0, mx0), mn1 = fmaxf(m1, mx1);
        float al0 = __expf(m0 - mn0), al1 = __expf(m1 - mn1);

        float rs0 = 0.f, rs1 = 0.f;
        #pragma unroll
        for (int nt = 0; nt < 8; nt++) {
            float p0 = __expf(s[nt][0] - mn0);
            float p1 = __expf(s[nt][1] - mn0);
            float p2 = __expf(s[nt][2] - mn1);
            float p3 = __expf(s[nt][3] - mn1);
            rs0 += p0 + p1; rs1 += p2 + p3;
            int colb = nt*8 + lr*2;
            *(__half2*)&sh[PS_OFF +  mrow     *PST + colb] = __floats2half2_rn(p0, p1);
            *(__half2*)&sh[PS_OFF + (mrow + 8)*PST + colb] = __floats2half2_rn(p2, p3);
        }
        rs0 += __shfl_xor_sync(0xffffffffu, rs0, 1);
        rs0 += __shfl_xor_sync(0xffffffffu, rs0, 2);
        rs1 += __shfl_xor_sync(0xffffffffu, rs1, 1);
        rs1 += __shfl_xor_sync(0xffffffffu, rs1, 2);
        l0 = l0*al0 + rs0;  l1 = l1*al1 + rs1;
        m0 = mn0;           m1 = mn1;
        #pragma unroll
        for (int nt = 0; nt < 16; nt++) {
            o[nt][0] *= al0; o[nt][1] *= al0;
            o[nt][2] *= al1; o[nt][3] *= al1;
        }

        __syncthreads();   // Ps written, all warps done reading K

        if (kt + 1 < nkt) { LOAD_K(kt + 1); cpwait<1>(); } // retire V(kt)
        else              { cpwait<0>(); }
        __syncthreads();   // V visible

        // -------- PV --------
        #pragma unroll
        for (int kk = 0; kk < 64; kk += 16) {
            unsigned a[4];
            ldsm4(a, &sh[PS_OFF + (w*16 + lidx)*PST + kk + lhi]);
            #pragma unroll
            for (int g = 0; g < 8; g++) {
                unsigned bv[4];
                int n0 = g*16;
                ldsm4t(bv, &sh[VS_OFF + (kk + lidx)*VST + n0 + lhi]);
                mma16(o[g*2],     a, bv[0], bv[1]);
                mma16(o[g*2 + 1], a, bv[2], bv[3]);
            }
        }
        __syncthreads();   // all warps done reading V

        if (kt + 1 < nkt) LOAD_V(kt + 1);
    }

    // -------- epilogue --------
    float inv0 = 1.f / l0, inv1 = 1.f / l1;
    __half* Ob = O + (size_t)(b*SEQ + q0)*QDIM + h*128;
    #pragma unroll
    for (int nt = 0; nt < 16; nt++) {
        int col = nt*8 + lr*2;
        *(__half2*)&Ob[(size_t) mrow     *QDIM + col] =
            __floats2half2_rn(o[nt][0]*inv0, o[nt][1]*inv0);
        *(__half2*)&Ob[(size_t)(mrow + 8)*QDIM + col] =
            __floats2half2_rn(o[nt][2]*inv1, o[nt][3]*inv1);
    }
    #undef LOAD_K
    #undef LOAD_V
}

// ---------------- launch ---------------------------------------------------
extern "C" void kernel_launch(void* const* d_in, const int* in_sizes, int n_in,
                              void* d_out, int out_size)
{
    const float* x  = (const float*)d_in[0];
    const float* Wq = (const float*)d_in[1];
    const float* Wk = (const float*)d_in[2];
    const float* Wv = (const float*)d_in[3];
    const float* Wo = (const float*)d_in[4];
    float* out = (float*)d_out;

    __half *xh, *wqh, *wkh, *wvh, *woh, *qh, *kh, *vh, *ah;
    cudaGetSymbolAddress((void**)&xh,  g_xh);
    cudaGetSymbolAddress((void**)&wqh, g_wqh);
    cudaGetSymbolAddress((void**)&wkh, g_wkh);
    cudaGetSymbolAddress((void**)&wvh, g_wvh);
    cudaGetSymbolAddress((void**)&woh, g_woh);
    cudaGetSymbolAddress((void**)&qh,  g_qh);
    cudaGetSymbolAddress((void**)&kh,  g_kh);
    cudaGetSymbolAddress((void**)&vh,  g_vh);
    cudaGetSymbolAddress((void**)&ah,  g_ah);

    rope_table_kernel<<<(SEQ*64 + 255)/256, 256>>>();

    // fp32 -> fp16 conversions
    f2h_kernel<<<(ROWS*HIDDEN/4 + 255)/256, 256>>>((const float4*)x,  (__half2*)xh,  ROWS*HIDDEN/4);
    f2h_kernel<<<(HIDDEN*QDIM/4 + 255)/256, 256>>>((const float4*)Wq, (__half2*)wqh, HIDDEN*QDIM/4);
    f2h_kernel<<<(HIDDEN*KVDIM/4 + 255)/256, 256>>>((const float4*)Wk, (__half2*)wkh, HIDDEN*KVDIM/4);
    f2h_kernel<<<(HIDDEN*KVDIM/4 + 255)/256, 256>>>((const float4*)Wv, (__half2*)wvh, HIDDEN*KVDIM/4);
    f2h_kernel<<<(QDIM*HIDDEN/4 + 255)/256, 256>>>((const float4*)Wo, (__half2*)woh, QDIM*HIDDEN/4);

    // projections (half out)
    gemm_f16<1><<<dim3(QDIM/128,  ROWS/128), 256>>>(xh, wqh, qh, ROWS, QDIM,  HIDDEN);
    gemm_f16<1><<<dim3(KVDIM/128, ROWS/128), 256>>>(xh, wkh, kh, ROWS, KVDIM, HIDDEN);
    gemm_f16<1><<<dim3(KVDIM/128, ROWS/128), 256>>>(xh, wvh, vh, ROWS, KVDIM, HIDDEN);

    // RoPE
    rope_apply_h<<<(ROWS*NH*64 + 255)/256, 256>>>(qh, NH);
    rope_apply_h<<<(ROWS*NKV*64 + 255)/256, 256>>>(kh, NKV);

    // attention
    cudaFuncSetAttribute(flash_f16, cudaFuncAttributeMaxDynamicSharedMemorySize,
                         FLASH_SMEM);
    flash_f16<<<dim3(SEQ/128, NH, BATCH), 256, FLASH_SMEM>>>(qh, kh, vh, ah);

    // output projection (float out)
    gemm_f16<0><<<dim3(QDIM/128, ROWS/128), 256>>>(ah, woh, out, ROWS, QDIM, HIDDEN);
}

// round 5
// speedup vs baseline: 6.9570x; 1.1843x over previous
#include <cuda_runtime.h>
#include <cuda_fp16.h>
#include <math.h>

#define SEQ    2048
#define BATCH  2
#define HIDDEN 2048
#define NH     16
#define NKV    4
#define HD     128
#define ROWS   (BATCH*SEQ)   /* 4096 */
#define QDIM   (NH*HD)       /* 2048 */
#define KVDIM  (NKV*HD)      /* 512  */

// ---------------- scratch (device globals: no allocation allowed) ----------
__device__ __half g_xh[ROWS*HIDDEN];    // 16 MB
__device__ __half g_wqh[HIDDEN*QDIM];   //  8 MB
__device__ __half g_wkh[HIDDEN*KVDIM];  //  2 MB
__device__ __half g_wvh[HIDDEN*KVDIM];  //  2 MB
__device__ __half g_woh[QDIM*HIDDEN];   //  8 MB
__device__ __half g_qh[ROWS*QDIM];      // 16 MB
__device__ __half g_kh[ROWS*KVDIM];     //  4 MB
__device__ __half g_vh[ROWS*KVDIM];     //  4 MB
__device__ __half g_ah[ROWS*QDIM];      // 16 MB
__device__ float  g_cos[SEQ*64];
__device__ float  g_sin[SEQ*64];

// ---------------- asm helpers ----------------------------------------------
__device__ __forceinline__ void ldsm4(unsigned* r, const void* p) {
    unsigned a = (unsigned)__cvta_generic_to_shared(p);
    asm volatile("ldmatrix.sync.aligned.m8n8.x4.shared.b16 {%0,%1,%2,%3}, [%4];"
        : "=r"(r[0]), "=r"(r[1]), "=r"(r[2]), "=r"(r[3]) : "r"(a));
}
__device__ __forceinline__ void ldsm4t(unsigned* r, const void* p) {
    unsigned a = (unsigned)__cvta_generic_to_shared(p);
    asm volatile("ldmatrix.sync.aligned.m8n8.x4.trans.shared.b16 {%0,%1,%2,%3}, [%4];"
        : "=r"(r[0]), "=r"(r[1]), "=r"(r[2]), "=r"(r[3]) : "r"(a));
}
__device__ __forceinline__ void mma16(float* d, const unsigned* a,
                                      unsigned b0, unsigned b1) {
    asm volatile("mma.sync.aligned.m16n8k16.row.col.f32.f16.f16.f32 "
        "{%0,%1,%2,%3}, {%4,%5,%6,%7}, {%8,%9}, {%0,%1,%2,%3};"
        : "+f"(d[0]), "+f"(d[1]), "+f"(d[2]), "+f"(d[3])
        : "r"(a[0]), "r"(a[1]), "r"(a[2]), "r"(a[3]), "r"(b0), "r"(b1));
}
__device__ __forceinline__ void cpa16(const void* smem, const void* g) {
    unsigned s = (unsigned)__cvta_generic_to_shared(smem);
    asm volatile("cp.async.cg.shared.global [%0], [%1], 16;" :: "r"(s), "l"(g));
}
__device__ __forceinline__ void cpcommit() { asm volatile("cp.async.commit_group;"); }
template<int N> __device__ __forceinline__ void cpwait() {
    asm volatile("cp.async.wait_group %0;" :: "n"(N));
}

// ---------------- fp32 -> fp16 convert -------------------------------------
__global__ void f2h_kernel(const float4* __restrict__ src,
                           __half2* __restrict__ dst, int n4) {
    int i = blockIdx.x * blockDim.x + threadIdx.x;
    if (i >= n4) return;
    float4 v = src[i];
    dst[2*i]   = __floats2half2_rn(v.x, v.y);
    dst[2*i+1] = __floats2half2_rn(v.z, v.w);
}

// ---------------- RoPE table -----------------------------------------------
__global__ void rope_table_kernel() {
    int i = blockIdx.x * blockDim.x + threadIdx.x;
    if (i >= SEQ*64) return;
    int s = i >> 6, d = i & 63;
    double invf = pow(10000.0, -((double)d) / 64.0);
    double ang  = (double)s * invf;
    double sn, cs;
    sincos(ang, &sn, &cs);
    g_cos[i] = (float)cs;
    g_sin[i] = (float)sn;
}

// ---------------- fused QKV projection + RoPE ------------------------------
// 128x128x32 tile, 8 warps (2x4), cp.async double buffer.
// bx 0..15 -> Q head bx (rope); 16..19 -> K head bx-16 (rope); 20..23 -> V.
#define AST 40
#define BST 136
#define CST 136
#define PROJ_SMEM (2*128*AST*2 + 2*32*BST*2)   /* 37888 bytes */

__global__ __launch_bounds__(256, 2) void proj_qkv(
    const __half* __restrict__ A,
    const __half* __restrict__ Wq, const __half* __restrict__ Wk,
    const __half* __restrict__ Wv,
    __half* __restrict__ Qo, __half* __restrict__ Ko, __half* __restrict__ Vo)
{
    __shared__ __align__(16) char smraw[PROJ_SMEM];
    __half* As = (__half*)smraw;                       // [2][128*AST]
    __half* Bs = (__half*)(smraw + 2*128*AST*2);       // [2][32*BST]
    __half* Cs = (__half*)smraw;                       // [128*CST] epilogue

    const int tid  = threadIdx.x;
    const int l    = tid & 31, warp = tid >> 5;
    const int wm = warp >> 2, wn = warp & 3;
    const int bx = blockIdx.x, by = blockIdx.y;
    const int lq = l >> 2, lr = l & 3;

    const __half* Bb; __half* Cb; int ldB; bool rope;
    if (bx < 16)      { Bb = Wq + bx*128;      ldB = QDIM;  Cb = Qo + bx*128;      rope = true; }
    else if (bx < 20) { Bb = Wk + (bx-16)*128; ldB = KVDIM; Cb = Ko + (bx-16)*128; rope = true; }
    else              { Bb = Wv + (bx-20)*128; ldB = KVDIM; Cb = Vo + (bx-20)*128; rope = false; }

    const __half* Ab = A + (size_t)(by*128)*HIDDEN;

    float acc[4][4][4];
    #pragma unroll
    for (int i = 0; i < 4; i++)
        #pragma unroll
        for (int j = 0; j < 4; j++)
            #pragma unroll
            for (int t = 0; t < 4; t++) acc[i][j][t] = 0.f;

    #define LOAD_STAGE(buf, k0) do {                                            \
        _Pragma("unroll")                                                       \
        for (int i = 0; i < 2; i++) {                                           \
            int c = tid + i*256;                                                \
            int m = c >> 2, kc = (c & 3) * 8;                                   \
            cpa16(&As[(buf)*128*AST + m*AST + kc], Ab + (size_t)m*HIDDEN + (k0) + kc); \
        }                                                                       \
        _Pragma("unroll")                                                       \
        for (int i = 0; i < 2; i++) {                                           \
            int c = tid + i*256;                                                \
            int k = c >> 4, nc = (c & 15) * 8;                                  \
            cpa16(&Bs[(buf)*32*BST + k*BST + nc], Bb + (size_t)((k0)+k)*ldB + nc); \
        }                                                                       \
        cpcommit();                                                             \
    } while (0)

    LOAD_STAGE(0, 0);

    const int nIter = HIDDEN / 32;
    for (int it = 0; it < nIter; it++) {
        int buf = it & 1;
        if (it + 1 < nIter) { LOAD_STAGE(buf ^ 1, (it+1)*32); cpwait<1>(); }
        else                { cpwait<0>(); }
        __syncthreads();

        #pragma unroll
        for (int kk = 0; kk < 32; kk += 16) {
            unsigned a[4][4], b[2][4];
            #pragma unroll
            for (int mt = 0; mt < 4; mt++) {
                int m0 = wm*64 + mt*16;
                ldsm4(a[mt], &As[buf*128*AST + (m0 + (l & 15))*AST + kk + ((l >> 4) << 3)]);
            }
            #pragma unroll
            for (int g = 0; g < 2; g++) {
                int n0 = wn*32 + g*16;
                ldsm4t(b[g], &Bs[buf*32*BST + (kk + (l & 15))*BST + n0 + ((l >> 4) << 3)]);
            }
            #pragma unroll
            for (int mt = 0; mt < 4; mt++)
                #pragma unroll
                for (int nt = 0; nt < 4; nt++) {
                    const unsigned* bg = b[nt >> 1];
                    if (nt & 1) mma16(acc[mt][nt], a[mt], bg[2], bg[3]);
                    else        mma16(acc[mt][nt], a[mt], bg[0], bg[1]);
                }
        }
        __syncthreads();
    }

    if (!rope) {
        // V: direct store
        #pragma unroll
        for (int mt = 0; mt < 4; mt++) {
            int row = by*128 + wm*64 + mt*16 + lq;
            #pragma unroll
            for (int nt = 0; nt < 4; nt++) {
                int col = wn*32 + nt*8 + lr*2;
                *(__half2*)&Cb[(size_t) row     *KVDIM + col] =
                    __floats2half2_rn(acc[mt][nt][0], acc[mt][nt][1]);
                *(__half2*)&Cb[(size_t)(row + 8)*KVDIM + col] =
                    __floats2half2_rn(acc[mt][nt][2], acc[mt][nt][3]);
            }
        }
        return;
    }

    // Q/K: stage tile to smem, apply RoPE, store
    const int ldC = (bx < 16) ? QDIM : KVDIM;
    #pragma unroll
    for (int mt = 0; mt < 4; mt++) {
        int row = wm*64 + mt*16 + lq;
        #pragma unroll
        for (int nt = 0; nt < 4; nt++) {
            int col = wn*32 + nt*8 + lr*2;
            *(__half2*)&Cs[ row     *CST + col] =
                __floats2half2_rn(acc[mt][nt][0], acc[mt][nt][1]);
            *(__half2*)&Cs[(row + 8)*CST + col] =
                __floats2half2_rn(acc[mt][nt][2], acc[mt][nt][3]);
        }
    }
    __syncthreads();

    #pragma unroll
    for (int i = 0; i < 32; i++) {
        int e   = tid + i*256;          // 0..8191  (half2 elements)
        int row = e >> 6;               // 0..127
        int c2  = (e & 63) * 2;         // even col 0..126
        int d   = c2 & 63;
        float2 x1 = __half22float2(*(__half2*)&Cs[row*CST + c2]);
        float2 x2 = __half22float2(*(__half2*)&Cs[row*CST + (c2 ^ 64)]);
        int sp = (by*128 + row) & (SEQ - 1);
        float c0 = g_cos[sp*64 + d],     s0 = g_sin[sp*64 + d];
        float c1 = g_cos[sp*64 + d + 1], s1 = g_sin[sp*64 + d + 1];
        float r0, r1;
        if (c2 < 64) { r0 = x1.x*c0 - x2.x*s0; r1 = x1.y*c1 - x2.y*s1; }
        else         { r0 = x1.x*c0 + x2.x*s0; r1 = x1.y*c1 + x2.y*s1; }
        *(__half2*)&Cb[(size_t)(by*128 + row)*ldC + c2] = __floats2half2_rn(r0, r1);
    }
    #undef LOAD_STAGE
}

// ---------------- Wo GEMM (fp32 out) ---------------------------------------
__global__ __launch_bounds__(256, 2) void gemm_f16_f32out(
    const __half* __restrict__ A, const __half* __restrict__ B,
    float* __restrict__ C, int M, int N, int K)
{
    __shared__ __half As[2][128*AST];
    __shared__ __half Bs[2][32*BST];

    const int tid  = threadIdx.x;
    const int l    = tid & 31, warp = tid >> 5;
    const int wm = warp >> 2, wn = warp & 3;
    const int bx = blockIdx.x, by = blockIdx.y;
    const int lq = l >> 2, lr = l & 3;

    const __half* Ab = A + (size_t)(by*128)*K;
    const __half* Bb = B + (size_t)bx*128;

    float acc[4][4][4];
    #pragma unroll
    for (int i = 0; i < 4; i++)
        #pragma unroll
        for (int j = 0; j < 4; j++)
            #pragma unroll
            for (int t = 0; t < 4; t++) acc[i][j][t] = 0.f;

    #define LOAD_STAGE(buf, k0) do {                                           \
        _Pragma("unroll")                                                      \
        for (int i = 0; i < 2; i++) {                                          \
            int c = tid + i*256;                                               \
            int m = c >> 2, kc = (c & 3) * 8;                                  \
            cpa16(&As[buf][m*AST + kc], Ab + (size_t)m*K + (k0) + kc);         \
        }                                                                      \
        _Pragma("unroll")                                                      \
        for (int i = 0; i < 2; i++) {                                          \
            int c = tid + i*256;                                               \
            int k = c >> 4, nc = (c & 15) * 8;                                 \
            cpa16(&Bs[buf][k*BST + nc], Bb + (size_t)((k0)+k)*N + nc);         \
        }                                                                      \
        cpcommit();                                                            \
    } while (0)

    LOAD_STAGE(0, 0);

    const int nIter = K / 32;
    for (int it = 0; it < nIter; it++) {
        int buf = it & 1;
        if (it + 1 < nIter) { LOAD_STAGE(buf ^ 1, (it+1)*32); cpwait<1>(); }
        else                { cpwait<0>(); }
        __syncthreads();

        #pragma unroll
        for (int kk = 0; kk < 32; kk += 16) {
            unsigned a[4][4], b[2][4];
            #pragma unroll
            for (int mt = 0; mt < 4; mt++) {
                int m0 = wm*64 + mt*16;
                ldsm4(a[mt], &As[buf][(m0 + (l & 15))*AST + kk + ((l >> 4) << 3)]);
            }
            #pragma unroll
            for (int g = 0; g < 2; g++) {
                int n0 = wn*32 + g*16;
                ldsm4t(b[g], &Bs[buf][(kk + (l & 15))*BST + n0 + ((l >> 4) << 3)]);
            }
            #pragma unroll
            for (int mt = 0; mt < 4; mt++)
                #pragma unroll
                for (int nt = 0; nt < 4; nt++) {
                    const unsigned* bg = b[nt >> 1];
                    if (nt & 1) mma16(acc[mt][nt], a[mt], bg[2], bg[3]);
                    else        mma16(acc[mt][nt], a[mt], bg[0], bg[1]);
                }
        }
        __syncthreads();
    }

    #pragma unroll
    for (int mt = 0; mt < 4; mt++) {
        int row = by*128 + wm*64 + mt*16 + lq;
        #pragma unroll
        for (int nt = 0; nt < 4; nt++) {
            int col = bx*128 + wn*32 + nt*8 + lr*2;
            *(float2*)&C[(size_t) row     *N + col] =
                make_float2(acc[mt][nt][0], acc[mt][nt][1]);
            *(float2*)&C[(size_t)(row + 8)*N + col] =
                make_float2(acc[mt][nt][2], acc[mt][nt][3]);
        }
    }
    #undef LOAD_STAGE
}

// ---------------- flash attention: BM=64, 4 warps, 3 CTAs/SM ---------------
#define QST 136
#define KST 136
#define VST 136
#define PST 72
#define QS_OFF 0
#define KS_OFF (64*QST)               /* 8704  */
#define VS_OFF (KS_OFF + 64*KST)      /* 17408 */
#define PS_OFF (VS_OFF + 64*VST)      /* 26112 */
#define FLASH_SMEM ((PS_OFF + 64*PST)*2)    /* 61440 bytes */

__global__ __launch_bounds__(128, 3) void flash_f16(
    const __half* __restrict__ Q, const __half* __restrict__ K,
    const __half* __restrict__ V, __half* __restrict__ O)
{
    extern __shared__ __half sh[];
    const int tid  = threadIdx.x;
    const int l    = tid & 31, w = tid >> 5;
    const int lq = l >> 2, lr = l & 3;
    const int qt = (gridDim.x - 1) - blockIdx.x;   // heavy tiles first
    const int h  = blockIdx.y, b = blockIdx.z;
    const int hk = h >> 2;
    const int q0 = qt * 64;
    const float scale = 0.08838834764831845f;

    const __half* Qbase = Q + (size_t)(b*SEQ + q0)*QDIM + h*128;
    const __half* Kb0   = K + (size_t)(b*SEQ)*KVDIM + hk*128;
    const __half* Vb0   = V + (size_t)(b*SEQ)*KVDIM + hk*128;

    // Q tile: 64 x 128 half = 1024 16B-chunks (m = c>>4, kc = (c&15)*8)
    #pragma unroll
    for (int i = 0; i < 8; i++) {
        int c = tid + i*128;
        int m = c >> 4, kc = (c & 15) * 8;
        cpa16(&sh[QS_OFF + m*QST + kc], Qbase + (size_t)m*QDIM + kc);
    }
    cpcommit();

    #define LOAD_K(kt) do {                                                    \
        const __half* kb = Kb0 + (size_t)(kt)*64*KVDIM;                        \
        _Pragma("unroll")                                                      \
        for (int i = 0; i < 8; i++) {                                          \
            int c = tid + i*128;                                               \
            int r = c >> 4, kc = (c & 15) * 8;                                 \
            cpa16(&sh[KS_OFF + r*KST + kc], kb + (size_t)r*KVDIM + kc);        \
        }                                                                      \
        cpcommit();                                                            \
    } while (0)
    #define LOAD_V(kt) do {                                                    \
        const __half* vb = Vb0 + (size_t)(kt)*64*KVDIM;                        \
        _Pragma("unroll")                                                      \
        for (int i = 0; i < 8; i++) {                                          \
            int c = tid + i*128;                                               \
            int r = c >> 4, kc = (c & 15) * 8;                                 \
            cpa16(&sh[VS_OFF + r*VST + kc], vb + (size_t)r*KVDIM + kc);        \
        }                                                                      \
        cpcommit();                                                            \
    } while (0)

    LOAD_K(0);
    LOAD_V(0);

    float o[16][4];
    #pragma unroll
    for (int nt = 0; nt < 16; nt++)
        #pragma unroll
        for (int t = 0; t < 4; t++) o[nt][t] = 0.f;
    float m0 = -INFINITY, m1 = -INFINITY, l0 = 0.f, l1 = 0.f;

    const int nkt  = qt + 1;
    const int mrow = w*16 + lq;
    const int lidx = l & 15, lhi = (l >> 4) << 3;

    for (int kt = 0; kt < nkt; kt++) {
        cpwait<1>();
        __syncthreads();

        // -------- scores S = Q K^T --------
        float s[8][4];
        #pragma unroll
        for (int nt = 0; nt < 8; nt++)
            #pragma unroll
            for (int t = 0; t < 4; t++) s[nt][t] = 0.f;

        #pragma unroll
        for (int kk = 0; kk < 128; kk += 16) {
            unsigned a[4];
            ldsm4(a, &sh[QS_OFF + (w*16 + lidx)*QST + kk + lhi]);
            #pragma unroll
            for (int g = 0; g < 4; g++) {
                unsigned bk[4];
                int n0 = g*16;
                ldsm4(bk, &sh[KS_OFF + (n0 + ((l >> 4) << 3) + (l & 7))*KST
                               + kk + (((l >> 3) & 1) << 3)]);
                mma16(s[g*2],     a, bk[0], bk[1]);
                mma16(s[g*2 + 1], a, bk[2], bk[3]);
            }
        }

        // -------- scale + causal mask --------
        const int r0 = q0 + mrow, r1 = r0 + 8;
        const bool need_mask = (kt == qt);
        #pragma unroll
        for (int nt = 0; nt < 8; nt++) {
            int col = kt*64 + nt*8 + lr*2;
            s[nt][0] *= scale; s[nt][1] *= scale;
            s[nt][2] *= scale; s[nt][3] *= scale;
            if (need_mask) {
                if (col     > r0) s[nt][0] = -INFINITY;
                if (col + 1 > r0) s[nt][1] = -INFINITY;
                if (col     > r1) s[nt][2] = -INFINITY;
                if (col + 1 > r1) s[nt][3] = -INFINITY;
            }
        }

        // -------- online softmax --------
        float mx0 = -INFINITY, mx1 = -INFINITY;
        #pragma unroll
        for (int nt = 0; nt < 8; nt++) {
            mx0 = fmaxf(mx0, fmaxf(s[nt][0], s[nt][1]));
            mx1 = fmaxf(mx1, fmaxf(s[nt][2], s[nt][3]));
        }
        mx0 = fmaxf(mx0, __shfl_xor_sync(0xffffffffu, mx0, 1));
        mx0 = fmaxf(mx0, __shfl_xor_sync(0xffffffffu, mx0, 2));
        mx1 = fmaxf(mx1, __shfl_xor_sync(0xffffffffu, mx1, 1));
        mx1 = fmaxf(mx1, __shfl_xor_sync(0xffffffffu, mx1, 2));
        float mn0 = fmaxf(m0, mx0), mn1 = fmaxf(m1, mx1);
        float al0 = __expf(m0 - mn0), al1 = __expf(m1 - mn1);

        float rs0 = 0.f, rs1 = 0.f;
        #pragma unroll
        for (int nt = 0; nt < 8; nt++) {
            float p0 = __expf(s[nt][0] - mn0);
            float p1 = __expf(s[nt][1] - mn0);
            float p2 = __expf(s[nt][2] - mn1);
            float p3 = __expf(s[nt][3] - mn1);
            rs0 += p0 + p1; rs1 += p2 + p3;
            int colb = nt*8 + lr*2;
            *(__half2*)&sh[PS_OFF +  mrow     *PST + colb] = __floats2half2_rn(p0, p1);
            *(__half2*)&sh[PS_OFF + (mrow + 8)*PST + colb] = __floats2half2_rn(p2, p3);
        }
        rs0 += __shfl_xor_sync(0xffffffffu, rs0, 1);
        rs0 += __shfl_xor_sync(0xffffffffu, rs0, 2);
        rs1 += __shfl_xor_sync(0xffffffffu, rs1, 1);
        rs1 += __shfl_xor_sync(0xffffffffu, rs1, 2);
        l0 = l0*al0 + rs0;  l1 = l1*al1 + rs1;
        m0 = mn0;           m1 = mn1;
        #pragma unroll
        for (int nt = 0; nt < 16; nt++) {
            o[nt][0] *= al0; o[nt][1] *= al0;
            o[nt][2] *= al1; o[nt][3] *= al1;
        }

        __syncthreads();   // Ps written, all warps done reading K

        if (kt + 1 < nkt) { LOAD_K(kt + 1); cpwait<1>(); } // retire V(kt)
        else              { cpwait<0>(); }
        __syncthreads();   // V visible

        // -------- PV --------
        #pragma unroll
        for (int kk = 0; kk < 64; kk += 16) {
            unsigned a[4];
            ldsm4(a, &sh[PS_OFF + (w*16 + lidx)*PST + kk + lhi]);
            #pragma unroll
            for (int g = 0; g < 8; g++) {
                unsigned bv[4];
                int n0 = g*16;
                ldsm4t(bv, &sh[VS_OFF + (kk + lidx)*VST + n0 + lhi]);
                mma16(o[g*2],     a, bv[0], bv[1]);
                mma16(o[g*2 + 1], a, bv[2], bv[3]);
            }
        }
        __syncthreads();   // all warps done reading V

        if (kt + 1 < nkt) LOAD_V(kt + 1);
    }

    // -------- epilogue --------
    float inv0 = 1.f / l0, inv1 = 1.f / l1;
    __half* Ob = O + (size_t)(b*SEQ + q0)*QDIM + h*128;
    #pragma unroll
    for (int nt = 0; nt < 16; nt++) {
        int col = nt*8 + lr*2;
        *(__half2*)&Ob[(size_t) mrow     *QDIM + col] =
            __floats2half2_rn(o[nt][0]*inv0, o[nt][1]*inv0);
        *(__half2*)&Ob[(size_t)(mrow + 8)*QDIM + col] =
            __floats2half2_rn(o[nt][2]*inv1, o[nt][3]*inv1);
    }
    #undef LOAD_K
    #undef LOAD_V
}

// ---------------- launch ---------------------------------------------------
extern "C" void kernel_launch(void* const* d_in, const int* in_sizes, int n_in,
                              void* d_out, int out_size)
{
    const float* x  = (const float*)d_in[0];
    const float* Wq = (const float*)d_in[1];
    const float* Wk = (const float*)d_in[2];
    const float* Wv = (const float*)d_in[3];
    const float* Wo = (const float*)d_in[4];
    float* out = (float*)d_out;

    __half *xh, *wqh, *wkh, *wvh, *woh, *qh, *kh, *vh, *ah;
    cudaGetSymbolAddress((void**)&xh,  g_xh);
    cudaGetSymbolAddress((void**)&wqh, g_wqh);
    cudaGetSymbolAddress((void**)&wkh, g_wkh);
    cudaGetSymbolAddress((void**)&wvh, g_wvh);
    cudaGetSymbolAddress((void**)&woh, g_woh);
    cudaGetSymbolAddress((void**)&qh,  g_qh);
    cudaGetSymbolAddress((void**)&kh,  g_kh);
    cudaGetSymbolAddress((void**)&vh,  g_vh);
    cudaGetSymbolAddress((void**)&ah,  g_ah);

    rope_table_kernel<<<(SEQ*64 + 255)/256, 256>>>();

    f2h_kernel<<<(ROWS*HIDDEN/4 + 255)/256, 256>>>((const float4*)x,  (__half2*)xh,  ROWS*HIDDEN/4);
    f2h_kernel<<<(HIDDEN*QDIM/4 + 255)/256, 256>>>((const float4*)Wq, (__half2*)wqh, HIDDEN*QDIM/4);
    f2h_kernel<<<(HIDDEN*KVDIM/4 + 255)/256, 256>>>((const float4*)Wk, (__half2*)wkh, HIDDEN*KVDIM/4);
    f2h_kernel<<<(HIDDEN*KVDIM/4 + 255)/256, 256>>>((const float4*)Wv, (__half2*)wvh, HIDDEN*KVDIM/4);
    f2h_kernel<<<(QDIM*HIDDEN/4 + 255)/256, 256>>>((const float4*)Wo, (__half2*)woh, QDIM*HIDDEN/4);

    // fused QKV projection + RoPE
    proj_qkv<<<dim3(24, ROWS/128), 256>>>(xh, wqh, wkh, wvh, qh, kh, vh);

    // attention
    cudaFuncSetAttribute(flash_f16, cudaFuncAttributeMaxDynamicSharedMemorySize,
                         FLASH_SMEM);
    flash_f16<<<dim3(SEQ/64, NH, BATCH), 128, FLASH_SMEM>>>(qh, kh, vh, ah);

    // output projection (float out)
    gemm_f16_f32out<<<dim3(QDIM/128, ROWS/128), 256>>>(ah, woh, out, ROWS, QDIM, HIDDEN);
}

// round 7
// speedup vs baseline: 7.2266x; 1.0388x over previous
#include <cuda_runtime.h>
#include <cuda_fp16.h>
#include <math.h>

#define SEQ    2048
#define BATCH  2
#define HIDDEN 2048
#define NH     16
#define NKV    4
#define HD     128
#define ROWS   (BATCH*SEQ)   /* 4096 */
#define QDIM   (NH*HD)       /* 2048 */
#define KVDIM  (NKV*HD)      /* 512  */

// ---------------- scratch (device globals: no allocation allowed) ----------
__device__ __half g_xh[ROWS*HIDDEN];    // 16 MB
__device__ __half g_wqh[HIDDEN*QDIM];   //  8 MB
__device__ __half g_wkh[HIDDEN*KVDIM];  //  2 MB
__device__ __half g_wvh[HIDDEN*KVDIM];  //  2 MB
__device__ __half g_woh[QDIM*HIDDEN];   //  8 MB
__device__ __half g_qh[ROWS*QDIM];      // 16 MB
__device__ __half g_kh[ROWS*KVDIM];     //  4 MB
__device__ __half g_vh[ROWS*KVDIM];     //  4 MB
__device__ __half g_ah[ROWS*QDIM];      // 16 MB
__device__ float  g_cos[SEQ*64];
__device__ float  g_sin[SEQ*64];

// ---------------- asm helpers ----------------------------------------------
__device__ __forceinline__ void ldsm4(unsigned* r, const void* p) {
    unsigned a = (unsigned)__cvta_generic_to_shared(p);
    asm volatile("ldmatrix.sync.aligned.m8n8.x4.shared.b16 {%0,%1,%2,%3}, [%4];"
        : "=r"(r[0]), "=r"(r[1]), "=r"(r[2]), "=r"(r[3]) : "r"(a));
}
__device__ __forceinline__ void ldsm4t(unsigned* r, const void* p) {
    unsigned a = (unsigned)__cvta_generic_to_shared(p);
    asm volatile("ldmatrix.sync.aligned.m8n8.x4.trans.shared.b16 {%0,%1,%2,%3}, [%4];"
        : "=r"(r[0]), "=r"(r[1]), "=r"(r[2]), "=r"(r[3]) : "r"(a));
}
__device__ __forceinline__ void mma16(float* d, const unsigned* a,
                                      unsigned b0, unsigned b1) {
    asm volatile("mma.sync.aligned.m16n8k16.row.col.f32.f16.f16.f32 "
        "{%0,%1,%2,%3}, {%4,%5,%6,%7}, {%8,%9}, {%0,%1,%2,%3};"
        : "+f"(d[0]), "+f"(d[1]), "+f"(d[2]), "+f"(d[3])
        : "r"(a[0]), "r"(a[1]), "r"(a[2]), "r"(a[3]), "r"(b0), "r"(b1));
}
__device__ __forceinline__ void cpa16(const void* smem, const void* g) {
    unsigned s = (unsigned)__cvta_generic_to_shared(smem);
    asm volatile("cp.async.cg.shared.global [%0], [%1], 16;" :: "r"(s), "l"(g));
}
__device__ __forceinline__ void cpcommit() { asm volatile("cp.async.commit_group;"); }
template<int N> __device__ __forceinline__ void cpwait() {
    asm volatile("cp.async.wait_group %0;" :: "n"(N));
}
// pack two fp32 into one fp16x2 register (lo = x, hi = y)
__device__ __forceinline__ unsigned packh2(float x, float y) {
    unsigned r;
    asm("cvt.rn.f16x2.f32 %0, %1, %2;" : "=r"(r) : "f"(y), "f"(x));
    return r;
}

// ---------------- fp32 -> fp16 convert -------------------------------------
__global__ void f2h_kernel(const float4* __restrict__ src,
                           __half2* __restrict__ dst, int n4) {
    int i = blockIdx.x * blockDim.x + threadIdx.x;
    if (i >= n4) return;
    float4 v = src[i];
    dst[2*i]   = __floats2half2_rn(v.x, v.y);
    dst[2*i+1] = __floats2half2_rn(v.z, v.w);
}

// ---------------- RoPE table -----------------------------------------------
__global__ void rope_table_kernel() {
    int i = blockIdx.x * blockDim.x + threadIdx.x;
    if (i >= SEQ*64) return;
    int s = i >> 6, d = i & 63;
    double invf = pow(10000.0, -((double)d) / 64.0);
    double ang  = (double)s * invf;
    double sn, cs;
    sincos(ang, &sn, &cs);
    g_cos[i] = (float)cs;
    g_sin[i] = (float)sn;
}

// ---------------- fused QKV projection + RoPE ------------------------------
#define AST 40
#define BST 136
#define CST 136
#define PROJ_SMEM (2*128*AST*2 + 2*32*BST*2)   /* 37888 bytes */

__global__ __launch_bounds__(256, 2) void proj_qkv(
    const __half* __restrict__ A,
    const __half* __restrict__ Wq, const __half* __restrict__ Wk,
    const __half* __restrict__ Wv,
    __half* __restrict__ Qo, __half* __restrict__ Ko, __half* __restrict__ Vo)
{
    __shared__ __align__(16) char smraw[PROJ_SMEM];
    __half* As = (__half*)smraw;                       // [2][128*AST]
    __half* Bs = (__half*)(smraw + 2*128*AST*2);       // [2][32*BST]
    __half* Cs = (__half*)smraw;                       // [128*CST] epilogue

    const int tid  = threadIdx.x;
    const int l    = tid & 31, warp = tid >> 5;
    const int wm = warp >> 2, wn = warp & 3;
    const int bx = blockIdx.x, by = blockIdx.y;
    const int lq = l >> 2, lr = l & 3;

    const __half* Bb; __half* Cb; int ldB; bool rope;
    if (bx < 16)      { Bb = Wq + bx*128;      ldB = QDIM;  Cb = Qo + bx*128;      rope = true; }
    else if (bx < 20) { Bb = Wk + (bx-16)*128; ldB = KVDIM; Cb = Ko + (bx-16)*128; rope = true; }
    else              { Bb = Wv + (bx-20)*128; ldB = KVDIM; Cb = Vo + (bx-20)*128; rope = false; }

    const __half* Ab = A + (size_t)(by*128)*HIDDEN;

    float acc[4][4][4];
    #pragma unroll
    for (int i = 0; i < 4; i++)
        #pragma unroll
        for (int j = 0; j < 4; j++)
            #pragma unroll
            for (int t = 0; t < 4; t++) acc[i][j][t] = 0.f;

    #define LOAD_STAGE(buf, k0) do {                                            \
        _Pragma("unroll")                                                       \
        for (int i = 0; i < 2; i++) {                                           \
            int c = tid + i*256;                                                \
            int m = c >> 2, kc = (c & 3) * 8;                                   \
            cpa16(&As[(buf)*128*AST + m*AST + kc], Ab + (size_t)m*HIDDEN + (k0) + kc); \
        }                                                                       \
        _Pragma("unroll")                                                       \
        for (int i = 0; i < 2; i++) {                                           \
            int c = tid + i*256;                                                \
            int k = c >> 4, nc = (c & 15) * 8;                                  \
            cpa16(&Bs[(buf)*32*BST + k*BST + nc], Bb + (size_t)((k0)+k)*ldB + nc); \
        }                                                                       \
        cpcommit();                                                             \
    } while (0)

    LOAD_STAGE(0, 0);

    const int nIter = HIDDEN / 32;
    for (int it = 0; it < nIter; it++) {
        int buf = it & 1;
        if (it + 1 < nIter) { LOAD_STAGE(buf ^ 1, (it+1)*32); cpwait<1>(); }
        else                { cpwait<0>(); }
        __syncthreads();

        #pragma unroll
        for (int kk = 0; kk < 32; kk += 16) {
            unsigned a[4][4], b[2][4];
            #pragma unroll
            for (int mt = 0; mt < 4; mt++) {
                int m0 = wm*64 + mt*16;
                ldsm4(a[mt], &As[buf*128*AST + (m0 + (l & 15))*AST + kk + ((l >> 4) << 3)]);
            }
            #pragma unroll
            for (int g = 0; g < 2; g++) {
                int n0 = wn*32 + g*16;
                ldsm4t(b[g], &Bs[buf*32*BST + (kk + (l & 15))*BST + n0 + ((l >> 4) << 3)]);
            }
            #pragma unroll
            for (int mt = 0; mt < 4; mt++)
                #pragma unroll
                for (int nt = 0; nt < 4; nt++) {
                    const unsigned* bg = b[nt >> 1];
                    if (nt & 1) mma16(acc[mt][nt], a[mt], bg[2], bg[3]);
                    else        mma16(acc[mt][nt], a[mt], bg[0], bg[1]);
                }
        }
        __syncthreads();
    }

    if (!rope) {
        #pragma unroll
        for (int mt = 0; mt < 4; mt++) {
            int row = by*128 + wm*64 + mt*16 + lq;
            #pragma unroll
            for (int nt = 0; nt < 4; nt++) {
                int col = wn*32 + nt*8 + lr*2;
                *(__half2*)&Cb[(size_t) row     *KVDIM + col] =
                    __floats2half2_rn(acc[mt][nt][0], acc[mt][nt][1]);
                *(__half2*)&Cb[(size_t)(row + 8)*KVDIM + col] =
                    __floats2half2_rn(acc[mt][nt][2], acc[mt][nt][3]);
            }
        }
        return;
    }

    const int ldC = (bx < 16) ? QDIM : KVDIM;
    #pragma unroll
    for (int mt = 0; mt < 4; mt++) {
        int row = wm*64 + mt*16 + lq;
        #pragma unroll
        for (int nt = 0; nt < 4; nt++) {
            int col = wn*32 + nt*8 + lr*2;
            *(__half2*)&Cs[ row     *CST + col] =
                __floats2half2_rn(acc[mt][nt][0], acc[mt][nt][1]);
            *(__half2*)&Cs[(row + 8)*CST + col] =
                __floats2half2_rn(acc[mt][nt][2], acc[mt][nt][3]);
        }
    }
    __syncthreads();

    #pragma unroll
    for (int i = 0; i < 32; i++) {
        int e   = tid + i*256;
        int row = e >> 6;
        int c2  = (e & 63) * 2;
        int d   = c2 & 63;
        float2 x1 = __half22float2(*(__half2*)&Cs[row*CST + c2]);
        float2 x2 = __half22float2(*(__half2*)&Cs[row*CST + (c2 ^ 64)]);
        int sp = (by*128 + row) & (SEQ - 1);
        float c0 = g_cos[sp*64 + d],     s0 = g_sin[sp*64 + d];
        float c1 = g_cos[sp*64 + d + 1], s1 = g_sin[sp*64 + d + 1];
        float r0, r1;
        if (c2 < 64) { r0 = x1.x*c0 - x2.x*s0; r1 = x1.y*c1 - x2.y*s1; }
        else         { r0 = x1.x*c0 + x2.x*s0; r1 = x1.y*c1 + x2.y*s1; }
        *(__half2*)&Cb[(size_t)(by*128 + row)*ldC + c2] = __floats2half2_rn(r0, r1);
    }
    #undef LOAD_STAGE
}

// ---------------- Wo GEMM (fp32 out) ---------------------------------------
__global__ __launch_bounds__(256, 2) void gemm_f16_f32out(
    const __half* __restrict__ A, const __half* __restrict__ B,
    float* __restrict__ C, int M, int N, int K)
{
    __shared__ __half As[2][128*AST];
    __shared__ __half Bs[2][32*BST];

    const int tid  = threadIdx.x;
    const int l    = tid & 31, warp = tid >> 5;
    const int wm = warp >> 2, wn = warp & 3;
    const int bx = blockIdx.x, by = blockIdx.y;
    const int lq = l >> 2, lr = l & 3;

    const __half* Ab = A + (size_t)(by*128)*K;
    const __half* Bb = B + (size_t)bx*128;

    float acc[4][4][4];
    #pragma unroll
    for (int i = 0; i < 4; i++)
        #pragma unroll
        for (int j = 0; j < 4; j++)
            #pragma unroll
            for (int t = 0; t < 4; t++) acc[i][j][t] = 0.f;

    #define LOAD_STAGE(buf, k0) do {                                           \
        _Pragma("unroll")                                                      \
        for (int i = 0; i < 2; i++) {                                          \
            int c = tid + i*256;                                               \
            int m = c >> 2, kc = (c & 3) * 8;                                  \
            cpa16(&As[buf][m*AST + kc], Ab + (size_t)m*K + (k0) + kc);         \
        }                                                                      \
        _Pragma("unroll")                                                      \
        for (int i = 0; i < 2; i++) {                                          \
            int c = tid + i*256;                                               \
            int k = c >> 4, nc = (c & 15) * 8;                                 \
            cpa16(&Bs[buf][k*BST + nc], Bb + (size_t)((k0)+k)*N + nc);         \
        }                                                                      \
        cpcommit();                                                            \
    } while (0)

    LOAD_STAGE(0, 0);

    const int nIter = K / 32;
    for (int it = 0; it < nIter; it++) {
        int buf = it & 1;
        if (it + 1 < nIter) { LOAD_STAGE(buf ^ 1, (it+1)*32); cpwait<1>(); }
        else                { cpwait<0>(); }
        __syncthreads();

        #pragma unroll
        for (int kk = 0; kk < 32; kk += 16) {
            unsigned a[4][4], b[2][4];
            #pragma unroll
            for (int mt = 0; mt < 4; mt++) {
                int m0 = wm*64 + mt*16;
                ldsm4(a[mt], &As[buf][(m0 + (l & 15))*AST + kk + ((l >> 4) << 3)]);
            }
            #pragma unroll
            for (int g = 0; g < 2; g++) {
                int n0 = wn*32 + g*16;
                ldsm4t(b[g], &Bs[buf][(kk + (l & 15))*BST + n0 + ((l >> 4) << 3)]);
            }
            #pragma unroll
            for (int mt = 0; mt < 4; mt++)
                #pragma unroll
                for (int nt = 0; nt < 4; nt++) {
                    const unsigned* bg = b[nt >> 1];
                    if (nt & 1) mma16(acc[mt][nt], a[mt], bg[2], bg[3]);
                    else        mma16(acc[mt][nt], a[mt], bg[0], bg[1]);
                }
        }
        __syncthreads();
    }

    #pragma unroll
    for (int mt = 0; mt < 4; mt++) {
        int row = by*128 + wm*64 + mt*16 + lq;
        #pragma unroll
        for (int nt = 0; nt < 4; nt++) {
            int col = bx*128 + wn*32 + nt*8 + lr*2;
            *(float2*)&C[(size_t) row     *N + col] =
                make_float2(acc[mt][nt][0], acc[mt][nt][1]);
            *(float2*)&C[(size_t)(row + 8)*N + col] =
                make_float2(acc[mt][nt][2], acc[mt][nt][3]);
        }
    }
    #undef LOAD_STAGE
}

// ---------------- flash attention: BM=64, P in registers, 2 syncs/kt -------
// smem: Q[64] + K[64] + V[2][64], strides 136. 69632 bytes -> 3 CTAs/SM.
#define QST 136
#define KST 136
#define VST 136
#define QS_OFF 0
#define KS_OFF (64*QST)               /* 8704  */
#define VS_OFF (KS_OFF + 64*KST)      /* 17408 */
#define FLASH_SMEM ((VS_OFF + 2*64*VST)*2)   /* 69632 bytes */

__global__ __launch_bounds__(128, 3) void flash_f16(
    const __half* __restrict__ Q, const __half* __restrict__ K,
    const __half* __restrict__ V, __half* __restrict__ O)
{
    extern __shared__ __half sh[];
    const int tid  = threadIdx.x;
    const int l    = tid & 31, w = tid >> 5;
    const int lq = l >> 2, lr = l & 3;
    const int qt = (gridDim.x - 1) - blockIdx.x;   // heavy tiles first
    const int h  = blockIdx.y, b = blockIdx.z;
    const int hk = h >> 2;
    const int q0 = qt * 64;
    const float sc2 = 0.08838834764831845f * 1.4426950408889634f; // scale*log2e

    const __half* Qbase = Q + (size_t)(b*SEQ + q0)*QDIM + h*128;
    const __half* Kb0   = K + (size_t)(b*SEQ)*KVDIM + hk*128;
    const __half* Vb0   = V + (size_t)(b*SEQ)*KVDIM + hk*128;

    // Q tile: 64 x 128 half = 1024 16B-chunks
    #pragma unroll
    for (int i = 0; i < 8; i++) {
        int c = tid + i*128;
        int m = c >> 4, kc = (c & 15) * 8;
        cpa16(&sh[QS_OFF + m*QST + kc], Qbase + (size_t)m*QDIM + kc);
    }
    cpcommit();

    #define LOAD_K(kt) do {                                                    \
        const __half* kb = Kb0 + (size_t)(kt)*64*KVDIM;                        \
        _Pragma("unroll")                                                      \
        for (int i = 0; i < 8; i++) {                                          \
            int c = tid + i*128;                                               \
            int r = c >> 4, kc = (c & 15) * 8;                                 \
            cpa16(&sh[KS_OFF + r*KST + kc], kb + (size_t)r*KVDIM + kc);        \
        }                                                                      \
        cpcommit();                                                            \
    } while (0)
    #define LOAD_V(kt, vb_idx) do {                                            \
        const __half* vb = Vb0 + (size_t)(kt)*64*KVDIM;                        \
        __half* vdst = &sh[VS_OFF + (vb_idx)*64*VST];                          \
        _Pragma("unroll")                                                      \
        for (int i = 0; i < 8; i++) {                                          \
            int c = tid + i*128;                                               \
            int r = c >> 4, kc = (c & 15) * 8;                                 \
            cpa16(&vdst[r*VST + kc], vb + (size_t)r*KVDIM + kc);               \
        }                                                                      \
        cpcommit();                                                            \
    } while (0)

    LOAD_K(0);
    LOAD_V(0, 0);

    float o[16][4];
    #pragma unroll
    for (int nt = 0; nt < 16; nt++)
        #pragma unroll
        for (int t = 0; t < 4; t++) o[nt][t] = 0.f;
    float m0 = -INFINITY, m1 = -INFINITY, l0 = 0.f, l1 = 0.f;

    const int nkt  = qt + 1;
    const int mrow = w*16 + lq;
    const int lidx = l & 15, lhi = (l >> 4) << 3;

    for (int kt = 0; kt < nkt; kt++) {
        cpwait<1>();       // K(kt) ready (kt=0 also retires Q); V(kt) pending
        __syncthreads();   // K visible to all; prev PV readers of V[(kt+1)&1] done

        // -------- scores S = Q K^T --------
        float s[8][4];
        #pragma unroll
        for (int nt = 0; nt < 8; nt++)
            #pragma unroll
            for (int t = 0; t < 4; t++) s[nt][t] = 0.f;

        #pragma unroll
        for (int kk = 0; kk < 128; kk += 16) {
            unsigned a[4];
            ldsm4(a, &sh[QS_OFF + (w*16 + lidx)*QST + kk + lhi]);
            #pragma unroll
            for (int g = 0; g < 4; g++) {
                unsigned bk[4];
                int n0 = g*16;
                ldsm4(bk, &sh[KS_OFF + (n0 + ((l >> 4) << 3) + (l & 7))*KST
                               + kk + (((l >> 3) & 1) << 3)]);
                mma16(s[g*2],     a, bk[0], bk[1]);
                mma16(s[g*2 + 1], a, bk[2], bk[3]);
            }
        }

        // -------- scale (exp2 domain) + causal mask --------
        const int r0 = q0 + mrow, r1 = r0 + 8;
        const bool need_mask = (kt == qt);
        #pragma unroll
        for (int nt = 0; nt < 8; nt++) {
            int col = kt*64 + nt*8 + lr*2;
            s[nt][0] *= sc2; s[nt][1] *= sc2;
            s[nt][2] *= sc2; s[nt][3] *= sc2;
            if (need_mask) {
                if (col     > r0) s[nt][0] = -INFINITY;
                if (col + 1 > r0) s[nt][1] = -INFINITY;
                if (col     > r1) s[nt][2] = -INFINITY;
                if (col + 1 > r1) s[nt][3] = -INFINITY;
            }
        }

        // -------- online softmax (base-2) --------
        float mx0 = -INFINITY, mx1 = -INFINITY;
        #pragma unroll
        for (int nt = 0; nt < 8; nt++) {
            mx0 = fmaxf(mx0, fmaxf(s[nt][0], s[nt][1]));
            mx1 = fmaxf(mx1, fmaxf(s[nt][2], s[nt][3]));
        }
        mx0 = fmaxf(mx0, __shfl_xor_sync(0xffffffffu, mx0, 1));
        mx0 = fmaxf(mx0, __shfl_xor_sync(0xffffffffu, mx0, 2));
        mx1 = fmaxf(mx1, __shfl_xor_sync(0xffffffffu, mx1, 1));
        mx1 = fmaxf(mx1, __shfl_xor_sync(0xffffffffu, mx1, 2));
        float mn0 = fmaxf(m0, mx0), mn1 = fmaxf(m1, mx1);
        float al0 = exp2f(m0 - mn0), al1 = exp2f(m1 - mn1);

        // P packed directly into PV A-fragments (C-frag of QK == A-frag of PV)
        unsigned aP[4][4];
        float rs0 = 0.f, rs1 = 0.f;
        #pragma unroll
        for (int nt = 0; nt < 8; nt++) {
            float p0 = exp2f(s[nt][0] - mn0);
            float p1 = exp2f(s[nt][1] - mn0);
            float p2 = exp2f(s[nt][2] - mn1);
            float p3 = exp2f(s[nt][3] - mn1);
            rs0 += p0 + p1; rs1 += p2 + p3;
            int g = nt >> 1;
            if (nt & 1) {
                aP[g][2] = packh2(p0, p1);
                aP[g][3] = packh2(p2, p3);
            } else {
                aP[g][0] = packh2(p0, p1);
                aP[g][1] = packh2(p2, p3);
            }
        }
        rs0 += __shfl_xor_sync(0xffffffffu, rs0, 1);
        rs0 += __shfl_xor_sync(0xffffffffu, rs0, 2);
        rs1 += __shfl_xor_sync(0xffffffffu, rs1, 1);
        rs1 += __shfl_xor_sync(0xffffffffu, rs1, 2);
        l0 = l0*al0 + rs0;  l1 = l1*al1 + rs1;
        m0 = mn0;           m1 = mn1;
        #pragma unroll
        for (int nt = 0; nt < 16; nt++) {
            o[nt][0] *= al0; o[nt][1] *= al0;
            o[nt][2] *= al1; o[nt][3] *= al1;
        }

        cpwait<0>();       // V(kt) ready
        __syncthreads();   // V visible; all warps done reading K(kt)

        if (kt + 1 < nkt) LOAD_K(kt + 1);   // overlaps with PV below

        // -------- PV (P from registers, V via ldmatrix.trans) --------
        const __half* Vs = &sh[VS_OFF + (kt & 1)*64*VST];
        #pragma unroll
        for (int g4 = 0; g4 < 4; g4++) {
            #pragma unroll
            for (int vg = 0; vg < 8; vg++) {
                unsigned bv[4];
                ldsm4t(bv, &Vs[(g4*16 + lidx)*VST + vg*16 + lhi]);
                mma16(o[vg*2],     aP[g4], bv[0], bv[1]);
                mma16(o[vg*2 + 1], aP[g4], bv[2], bv[3]);
            }
        }

        if (kt + 1 < nkt) LOAD_V(kt + 1, (kt + 1) & 1);
    }

    // -------- epilogue --------
    float inv0 = 1.f / l0, inv1 = 1.f / l1;
    __half* Ob = O + (size_t)(b*SEQ + q0)*QDIM + h*128;
    #pragma unroll
    for (int nt = 0; nt < 16; nt++) {
        int col = nt*8 + lr*2;
        *(__half2*)&Ob[(size_t) mrow     *QDIM + col] =
            __floats2half2_rn(o[nt][0]*inv0, o[nt][1]*inv0);
        *(__half2*)&Ob[(size_t)(mrow + 8)*QDIM + col] =
            __floats2half2_rn(o[nt][2]*inv1, o[nt][3]*inv1);
    }
    #undef LOAD_K
    #undef LOAD_V
}

// ---------------- launch ---------------------------------------------------
extern "C" void kernel_launch(void* const* d_in, const int* in_sizes, int n_in,
                              void* d_out, int out_size)
{
    const float* x  = (const float*)d_in[0];
    const float* Wq = (const float*)d_in[1];
    const float* Wk = (const float*)d_in[2];
    const float* Wv = (const float*)d_in[3];
    const float* Wo = (const float*)d_in[4];
    float* out = (float*)d_out;

    __half *xh, *wqh, *wkh, *wvh, *woh, *qh, *kh, *vh, *ah;
    cudaGetSymbolAddress((void**)&xh,  g_xh);
    cudaGetSymbolAddress((void**)&wqh, g_wqh);
    cudaGetSymbolAddress((void**)&wkh, g_wkh);
    cudaGetSymbolAddress((void**)&wvh, g_wvh);
    cudaGetSymbolAddress((void**)&woh, g_woh);
    cudaGetSymbolAddress((void**)&qh,  g_qh);
    cudaGetSymbolAddress((void**)&kh,  g_kh);
    cudaGetSymbolAddress((void**)&vh,  g_vh);
    cudaGetSymbolAddress((void**)&ah,  g_ah);

    rope_table_kernel<<<(SEQ*64 + 255)/256, 256>>>();

    f2h_kernel<<<(ROWS*HIDDEN/4 + 255)/256, 256>>>((const float4*)x,  (__half2*)xh,  ROWS*HIDDEN/4);
    f2h_kernel<<<(HIDDEN*QDIM/4 + 255)/256, 256>>>((const float4*)Wq, (__half2*)wqh, HIDDEN*QDIM/4);
    f2h_kernel<<<(HIDDEN*KVDIM/4 + 255)/256, 256>>>((const float4*)Wk, (__half2*)wkh, HIDDEN*KVDIM/4);
    f2h_kernel<<<(HIDDEN*KVDIM/4 + 255)/256, 256>>>((const float4*)Wv, (__half2*)wvh, HIDDEN*KVDIM/4);
    f2h_kernel<<<(QDIM*HIDDEN/4 + 255)/256, 256>>>((const float4*)Wo, (__half2*)woh, QDIM*HIDDEN/4);

    proj_qkv<<<dim3(24, ROWS/128), 256>>>(xh, wqh, wkh, wvh, qh, kh, vh);

    cudaFuncSetAttribute(flash_f16, cudaFuncAttributeMaxDynamicSharedMemorySize,
                         FLASH_SMEM);
    flash_f16<<<dim3(SEQ/64, NH, BATCH), 128, FLASH_SMEM>>>(qh, kh, vh, ah);

    gemm_f16_f32out<<<dim3(QDIM/128, ROWS/128), 256>>>(ah, woh, out, ROWS, QDIM, HIDDEN);
}